// round 12
// baseline (speedup 1.0000x reference)
#include <cuda_runtime.h>
#include <cstdint>

// ---------------------------------------------------------------------------
// Fully-fused recurrent relational network, v8b (re-bench of v8 after infra
// flake — source functionally identical; v8 = v6 structure at 3 CTAs/SM).
// CTA = 4 graphs, 4 warps; warp w owns graph w (rows w*8..w*8+7), lane owns
// cols lane*4..+3; each THREAD owns all 8 rows x its 4 cols.
// smem = h(16K) + S-scratch(16K) + one 3x8KB cp.async W ring = 56KB.
// xw (step-invariant x @ node_w1[0:128] + node_b1) lives in an 8MB __device__
// scratch (L2-resident; read back 8x per CTA, own-thread coalesced float4s).
// Weight staging is ONE continuous cp.async chain across all GEMMs: each
// GEMM's tail iterations prefetch the next GEMM's first chunks, so the async
// pipe never drains (no per-GEMM prologue bubble).
// ---------------------------------------------------------------------------

#define THREADS 128
#define NG      4
#define MROWS   32
#define BS      2048
#define NSTEPS  8
#define H       128
#define KCH     16                      // k-rows per staged chunk
#define NCHK    (H / KCH)               // 8 chunks per GEMM
#define CHF     (KCH * H)               // 2048 floats = 8KB per chunk

__device__ float g_xw[BS * 8 * H];      // 8MB step-invariant xw scratch

union F2 { float2 f; unsigned long long u; };

__device__ __forceinline__ F2 f2fma(F2 a, F2 b, F2 c) {
    F2 d;
    asm("fma.rn.f32x2 %0, %1, %2, %3;" : "=l"(d.u) : "l"(a.u), "l"(b.u), "l"(c.u));
    return d;
}
__device__ __forceinline__ F2 f2bcast(float x) {
    F2 r; unsigned xi = __float_as_uint(x);
    asm("mov.b64 %0, {%1, %1};" : "=l"(r.u) : "r"(xi));
    return r;
}
__device__ __forceinline__ F2 f2mk(float x, float y) { F2 r; r.f.x = x; r.f.y = y; return r; }

__device__ __forceinline__ void cp_commit() { asm volatile("cp.async.commit_group;" ::: "memory"); }
__device__ __forceinline__ void cp_wait1()  { asm volatile("cp.async.wait_group 1;"  ::: "memory"); }
__device__ __forceinline__ void cp_wait0()  { asm volatile("cp.async.wait_group 0;"  ::: "memory"); }

__device__ __forceinline__ float f4c(const float4& v, int k) {
    return k == 0 ? v.x : k == 1 ? v.y : k == 2 ? v.z : v.w;
}

// Stage one 16x128 chunk (8KB) at src into ws: 512 float4, 4 per thread.
__device__ __forceinline__ void stage_chunk(float* ws, const float* __restrict__ src,
                                            int t) {
    const float4* s = reinterpret_cast<const float4*>(src) + t;
    unsigned dst = (unsigned)__cvta_generic_to_shared(ws) + t * 16;
#pragma unroll
    for (int i = 0; i < 2; ++i) {
        asm volatile("cp.async.cg.shared.global [%0], [%1], 16;"
                     :: "r"(dst + i * 2048), "l"(s + i * 128) : "memory");
    }
#pragma unroll
    for (int i = 2; i < 4; ++i) {
        asm volatile("cp.async.cg.shared.global [%0], [%1], 16;"
                     :: "r"(dst + i * 2048), "l"(s + i * 128) : "memory");
    }
}

__device__ __forceinline__ void chunk_fma(const float* __restrict__ in,
                                          const float* __restrict__ wb,
                                          F2 (&acc)[8][2], int r0, int c0, int kb) {
#pragma unroll
    for (int kk = 0; kk < KCH; kk += 4) {
        float4 a[8];
#pragma unroll
        for (int r = 0; r < 8; ++r)
            a[r] = *reinterpret_cast<const float4*>(in + (r0 + r) * H + kb + kk);
#pragma unroll
        for (int k = 0; k < 4; ++k) {
            float4 wv = *reinterpret_cast<const float4*>(wb + (kk + k) * H + c0);
            F2 w0 = f2mk(wv.x, wv.y), w1 = f2mk(wv.z, wv.w);
#pragma unroll
            for (int r = 0; r < 8; ++r) {
                F2 b = f2bcast(f4c(a[r], k));
                acc[r][0] = f2fma(b, w0, acc[r][0]);
                acc[r][1] = f2fma(b, w1, acc[r][1]);
            }
        }
    }
}

// acc += in(own rows) @ W.  Continuous chain: chunk ch's buffer is `slot`
// (carried across calls); each iteration prefetches two chunks ahead — from W
// while inside this GEMM, from Wnext for the last two iterations.  wait1 keeps
// exactly one prefetch in flight while guaranteeing the compute chunk landed.
__device__ __forceinline__ void gemm_chain(const float* __restrict__ in,
                                           const float* __restrict__ W,
                                           const float* __restrict__ Wnext,
                                           F2 (&acc)[8][2], int r0, int c0, int t,
                                           float* ws, int& slot) {
#pragma unroll
    for (int ch = 0; ch < NCHK; ++ch) {
        cp_wait1();
        __syncthreads();                 // all warps past the buffer being restaged
        const float* src = (ch + 2 < NCHK) ? (W + (ch + 2) * CHF)
                                           : (Wnext + (ch + 2 - NCHK) * CHF);
        int stslot = slot + 2; if (stslot >= 3) stslot -= 3;
        stage_chunk(ws + stslot * CHF, src, t);
        cp_commit();
        chunk_fma(in, ws + slot * CHF, acc, r0, c0, ch * KCH);
        slot = (slot == 2) ? 0 : slot + 1;
    }
}

__device__ __forceinline__ void acc_zero(F2 (&acc)[8][2]) {
#pragma unroll
    for (int r = 0; r < 8; ++r) { acc[r][0] = f2mk(0.f, 0.f); acc[r][1] = f2mk(0.f, 0.f); }
}
__device__ __forceinline__ void acc_bias(F2 (&acc)[8][2], const float* __restrict__ bias,
                                         int c0, float s) {
    float4 b = *reinterpret_cast<const float4*>(bias + c0);
#pragma unroll
    for (int r = 0; r < 8; ++r) {
        acc[r][0] = f2mk(b.x * s, b.y * s);
        acc[r][1] = f2mk(b.z * s, b.w * s);
    }
}
__device__ __forceinline__ void acc_from_smem(F2 (&acc)[8][2], const float* __restrict__ src,
                                              int r0, int c0) {
#pragma unroll
    for (int r = 0; r < 8; ++r) {
        float4 v = *reinterpret_cast<const float4*>(src + (r0 + r) * H + c0);
        acc[r][0] = f2mk(v.x, v.y);
        acc[r][1] = f2mk(v.z, v.w);
    }
}
__device__ __forceinline__ void acc_store(float* __restrict__ out, F2 (&acc)[8][2],
                                          int r0, int c0, bool relu) {
#pragma unroll
    for (int r = 0; r < 8; ++r) {
        float4 v = make_float4(acc[r][0].f.x, acc[r][0].f.y, acc[r][1].f.x, acc[r][1].f.y);
        if (relu) {
            v.x = fmaxf(v.x, 0.f); v.y = fmaxf(v.y, 0.f);
            v.z = fmaxf(v.z, 0.f); v.w = fmaxf(v.w, 0.f);
        }
        *reinterpret_cast<float4*>(out + (r0 + r) * H + c0) = v;
    }
}

__global__ void __launch_bounds__(THREADS, 3)
rrn_kernel(const int* __restrict__ sources, const int* __restrict__ targets,
           const int* __restrict__ types, const int* __restrict__ diffs,
           const int* __restrict__ question,
           const float* __restrict__ pre_w1, const float* __restrict__ pre_b1,
           const float* __restrict__ pre_w2, const float* __restrict__ pre_b2,
           const float* __restrict__ msg_w1, const float* __restrict__ msg_b1,
           const float* __restrict__ msg_w2, const float* __restrict__ msg_b2,
           const float* __restrict__ node_w1, const float* __restrict__ node_b1,
           const float* __restrict__ node_w2, const float* __restrict__ node_b2,
           const float* __restrict__ out_w1, const float* __restrict__ out_b1,
           const float* __restrict__ out_w2, const float* __restrict__ out_b2,
           float* __restrict__ out)
{
    extern __shared__ float sm[];
    float* sh_h = sm;                     // current hidden state (16KB)
    float* sh_S = sm + 4096;              // scratch: feats / A / S / m_agg / hidden / pooled
    float* ws   = sm + 8192;              // cp.async W ring: 3 x 8KB

    const int t    = threadIdx.x;
    const int cta  = blockIdx.x;
    const int warp = t >> 5;              // == graph within CTA
    const int r0   = warp * 8;
    const int c0   = (t & 31) * 4;
    const int node0 = cta * MROWS;

    const float* msg_w1b  = msg_w1 + 128 * H;
    const float* node_w1b = node_w1 + 128 * H;
    const float* node_w1c = node_w1 + 256 * H;

    // ---- pre-MLP hidden = relu(one-hot gather of pre_w1 rows + b1) -> sh_S
    {
        const float b1 = pre_b1[t];
        for (int m = 0; m < MROWS; ++m) {
            const int node = node0 + m;
            const int b  = node >> 3;
            const int s  = sources[node];
            const int tg = targets[node];
            const int ty = types[node];
            const int d  = diffs[node];
            const int q  = question[b];
            float v = pre_w1[s * H + t] + pre_w1[(8 + tg) * H + t]
                    + pre_w1[(16 + ty) * H + t] + pre_w1[(19 + d) * H + t]
                    + pre_w1[(119 + q) * H + t] + b1;
            sh_S[m * H + t] = fmaxf(v, 0.f);
        }
    }
    __syncthreads();

    // ---- start the continuous weight chain: prime with pre_w2 chunks 0,1
    int slot = 0;
    stage_chunk(ws, pre_w2, t);             cp_commit();
    stage_chunk(ws + CHF, pre_w2 + CHF, t); cp_commit();

    // ---- x = hidden @ pre_w2 + pre_b2 -> sh_h  (h0 = x)
    {
        F2 acc[8][2];
        acc_bias(acc, pre_b2, c0, 1.0f);
        gemm_chain(sh_S, pre_w2, node_w1, acc, r0, c0, t, ws, slot);
        acc_store(sh_h, acc, r0, c0, false);
        __syncwarp();
    }

    // ---- xw = x @ node_w1[0:128] + node_b1 -> g_xw (step-invariant, global)
    {
        F2 acc[8][2];
        acc_bias(acc, node_b1, c0, 1.0f);
        gemm_chain(sh_h, node_w1, msg_w1, acc, r0, c0, t, ws, slot);
        acc_store(g_xw + node0 * H, acc, r0, c0, false);
    }

    const float4 b1v = *reinterpret_cast<const float4*>(msg_b1 + c0);
    const float bias1[4] = {b1v.x, b1v.y, b1v.z, b1v.w};

    for (int step = 0; step < NSTEPS; ++step) {
        // A = h @ msg_w1[0:128]  -> park in sh_S (own slots)
        {
            F2 acc[8][2];
            acc_zero(acc);
            gemm_chain(sh_h, msg_w1, msg_w1b, acc, r0, c0, t, ws, slot);
            acc_store(sh_S, acc, r0, c0, false);
        }
        // B = h @ msg_w1[128:256]  (registers)
        F2 accB[8][2];
        acc_zero(accB);
        gemm_chain(sh_h, msg_w1b, msg_w2, accB, r0, c0, t, ws, slot);

        // S_i = sum_{j != i} relu(A_i + B_j + b1): thread-local (8 rows x 4 cols)
        {
            F2 accA[8][2];
            acc_from_smem(accA, sh_S, r0, c0);   // reload A (same thread wrote it)
#pragma unroll
            for (int cc = 0; cc < 4; ++cc) {
                const int p = cc >> 1, hl = cc & 1;
                float A[8], Bv[8];
#pragma unroll
                for (int r = 0; r < 8; ++r) {
                    A[r]  = hl ? accA[r][p].f.y : accA[r][p].f.x;
                    Bv[r] = hl ? accB[r][p].f.y : accB[r][p].f.x;
                }
                const float bc = bias1[cc];
#pragma unroll
                for (int i = 0; i < 8; ++i) {
                    float s = 0.f;
#pragma unroll
                    for (int j = 0; j < 8; ++j) s += fmaxf(A[i] + Bv[j] + bc, 0.f);
                    s -= fmaxf(A[i] + Bv[i] + bc, 0.f);    // drop self-edge
                    if (hl) accA[i][p].f.y = s; else accA[i][p].f.x = s;
                }
            }
            acc_store(sh_S, accA, r0, c0, false);          // S -> own slots
            __syncwarp();
        }

        // m_agg = S @ msg_w2 + 7*msg_b2 -> sh_S (own slots)
        {
            F2 acc[8][2];
            acc_bias(acc, msg_b2, c0, 7.0f);
            gemm_chain(sh_S, msg_w2, node_w1b, acc, r0, c0, t, ws, slot);
            acc_store(sh_S, acc, r0, c0, false);
            __syncwarp();
        }

        // hidden = relu(xw + h@Wn1b + m_agg@Wn1c) -> sh_S (own slots)
        {
            F2 acc[8][2];
#pragma unroll
            for (int r = 0; r < 8; ++r) {    // acc := xw (own tile, coalesced LDG)
                float4 v = *reinterpret_cast<const float4*>(
                    g_xw + (node0 + r0 + r) * H + c0);
                acc[r][0] = f2mk(v.x, v.y);
                acc[r][1] = f2mk(v.z, v.w);
            }
            gemm_chain(sh_h, node_w1b, node_w1c, acc, r0, c0, t, ws, slot);
            gemm_chain(sh_S, node_w1c, node_w2, acc, r0, c0, t, ws, slot);
            acc_store(sh_S, acc, r0, c0, true);
            __syncwarp();
        }

        // h_new = hidden @ node_w2 + node_b2 -> sh_h ; pooled from regs
        {
            F2 acc[8][2];
            acc_bias(acc, node_b2, c0, 1.0f);
            const float* nextW = (step + 1 < NSTEPS) ? msg_w1 : pre_w2;  // dummy at end
            gemm_chain(sh_S, node_w2, nextW, acc, r0, c0, t, ws, slot);
            acc_store(sh_h, acc, r0, c0, false);
            float4 pool = make_float4(0.f, 0.f, 0.f, 0.f);
#pragma unroll
            for (int r = 0; r < 8; ++r) {
                pool.x += acc[r][0].f.x; pool.y += acc[r][0].f.y;
                pool.z += acc[r][1].f.x; pool.w += acc[r][1].f.y;
            }
            __syncthreads();               // all warps done reading sh_S rows
            *reinterpret_cast<float4*>(sh_S + warp * H + c0) = pool;  // row g = graph g
        }
        __syncthreads();

        // out hidden = relu(pooled @ out_w1 + out_b1) -> sh_S rows 4..7
        {
            float acc[NG];
            const float ob = out_b1[t];
#pragma unroll
            for (int g = 0; g < NG; ++g) acc[g] = ob;
#pragma unroll 8
            for (int k = 0; k < H; ++k) {
                const float w = out_w1[k * H + t];
#pragma unroll
                for (int g = 0; g < NG; ++g) acc[g] += sh_S[g * H + k] * w;
            }
#pragma unroll
            for (int g = 0; g < NG; ++g) sh_S[(4 + g) * H + t] = fmaxf(acc[g], 0.f);
        }
        __syncthreads();

        // logits = oh @ out_w2 + out_b2 -> gmem [step][bs][100]
        if (t < 100) {
            float acc[NG];
            const float ob = out_b2[t];
#pragma unroll
            for (int g = 0; g < NG; ++g) acc[g] = ob;
#pragma unroll 8
            for (int k = 0; k < H; ++k) {
                const float w = out_w2[k * 100 + t];
#pragma unroll
                for (int g = 0; g < NG; ++g) acc[g] += sh_S[(4 + g) * H + k] * w;
            }
#pragma unroll
            for (int g = 0; g < NG; ++g)
                out[(step * BS + cta * NG + g) * 100 + t] = acc[g];
        }
        // next iteration's first gemm_chain begins with wait1+syncthreads
    }

    cp_wait0();                            // drain outstanding prefetches before exit
}

extern "C" void kernel_launch(void* const* d_in, const int* in_sizes, int n_in,
                              void* d_out, int out_size) {
    (void)in_sizes; (void)n_in; (void)out_size;
    const int*   sources  = (const int*)  d_in[0];
    const int*   targets  = (const int*)  d_in[1];
    const int*   types    = (const int*)  d_in[2];
    const int*   diffs    = (const int*)  d_in[3];
    const int*   question = (const int*)  d_in[4];
    const float* pre_w1   = (const float*)d_in[5];
    const float* pre_b1   = (const float*)d_in[6];
    const float* pre_w2   = (const float*)d_in[7];
    const float* pre_b2   = (const float*)d_in[8];
    const float* msg_w1   = (const float*)d_in[9];
    const float* msg_b1   = (const float*)d_in[10];
    const float* msg_w2   = (const float*)d_in[11];
    const float* msg_b2   = (const float*)d_in[12];
    const float* node_w1  = (const float*)d_in[13];
    const float* node_b1  = (const float*)d_in[14];
    const float* node_w2  = (const float*)d_in[15];
    const float* node_b2  = (const float*)d_in[16];
    const float* out_w1   = (const float*)d_in[17];
    const float* out_b1   = (const float*)d_in[18];
    const float* out_w2   = (const float*)d_in[19];
    const float* out_b2   = (const float*)d_in[20];

    const size_t smem = (2 * 4096 + 3 * CHF) * sizeof(float);  // 32KB + 24KB = 56KB
    cudaFuncSetAttribute(rrn_kernel, cudaFuncAttributeMaxDynamicSharedMemorySize,
                         (int)smem);

    rrn_kernel<<<BS / NG, THREADS, smem>>>(
        sources, targets, types, diffs, question,
        pre_w1, pre_b1, pre_w2, pre_b2,
        msg_w1, msg_b1, msg_w2, msg_b2,
        node_w1, node_b1, node_w2, node_b2,
        out_w1, out_b1, out_w2, out_b2,
        (float*)d_out);
}

// round 13
// speedup vs baseline: 1.3550x; 1.3550x over previous
#include <cuda_runtime.h>
#include <cstdint>

// ---------------------------------------------------------------------------
// Fully-fused recurrent relational network, v9 = v4 (proven 770us structure:
// per-GEMM cp.async rings, dual A/B GEMM, xw in smem, 72KB, 3 CTAs/SM)
// + ONE change: the node-update's two accumulating GEMMs (h@Wn1b + m_agg@Wn1c)
// fused into a single dual-INPUT ring pass -> 5 GEMM passes/step become 4,
// removing 16 chunk barriers + one prologue drain per step. Register peak
// unchanged (the A/B dual pass remains the max).
// CTA = 4 graphs (32 rows), 128 threads = 4 warps; warp w owns rows w*8..+7,
// lane owns cols lane*4..+3.
// ---------------------------------------------------------------------------

#define THREADS 128
#define NG      4
#define MROWS   32
#define BS      2048
#define NSTEPS  8
#define H       128
#define KCH     8                       // k-rows per staged chunk
#define NCHK    (H / KCH)               // 16 chunks per GEMM
#define CHF     (KCH * H)               // 1024 floats = 4KB per chunk

union F2 { float2 f; unsigned long long u; };

__device__ __forceinline__ F2 f2fma(F2 a, F2 b, F2 c) {
    F2 d;
    asm("fma.rn.f32x2 %0, %1, %2, %3;" : "=l"(d.u) : "l"(a.u), "l"(b.u), "l"(c.u));
    return d;
}
__device__ __forceinline__ F2 f2bcast(float x) {
    F2 r; unsigned xi = __float_as_uint(x);
    asm("mov.b64 %0, {%1, %1};" : "=l"(r.u) : "r"(xi));
    return r;
}
__device__ __forceinline__ F2 f2mk(float x, float y) { F2 r; r.f.x = x; r.f.y = y; return r; }

__device__ __forceinline__ void cp_commit() { asm volatile("cp.async.commit_group;" ::: "memory"); }
__device__ __forceinline__ void cp_wait1()  { asm volatile("cp.async.wait_group 1;"  ::: "memory"); }

__device__ __forceinline__ float f4c(const float4& v, int k) {
    return k == 0 ? v.x : k == 1 ? v.y : k == 2 ? v.z : v.w;
}

// Stage one 8x128 chunk (4KB): 256 float4, 2 per thread, coalesced.
__device__ __forceinline__ void stage_chunk(float* ws, const float* __restrict__ W,
                                            int chunk, int t) {
    const float4* src = reinterpret_cast<const float4*>(W + chunk * CHF) + t;
    unsigned dst = (unsigned)__cvta_generic_to_shared(ws) + t * 16;
#pragma unroll
    for (int i = 0; i < 2; ++i) {
        asm volatile("cp.async.cg.shared.global [%0], [%1], 16;"
                     :: "r"(dst + i * 2048), "l"(src + i * 128) : "memory");
    }
}

__device__ __forceinline__ void chunk_fma(const float* __restrict__ in,
                                          const float* __restrict__ wb,
                                          F2 (&acc)[8][2], int r0, int c0, int kb) {
#pragma unroll
    for (int kk = 0; kk < KCH; kk += 4) {
        float4 a[8];
#pragma unroll
        for (int r = 0; r < 8; ++r)
            a[r] = *reinterpret_cast<const float4*>(in + (r0 + r) * H + kb + kk);
#pragma unroll
        for (int k = 0; k < 4; ++k) {
            float4 wv = *reinterpret_cast<const float4*>(wb + (kk + k) * H + c0);
            F2 w0 = f2mk(wv.x, wv.y), w1 = f2mk(wv.z, wv.w);
#pragma unroll
            for (int r = 0; r < 8; ++r) {
                F2 b = f2bcast(f4c(a[r], k));
                acc[r][0] = f2fma(b, w0, acc[r][0]);
                acc[r][1] = f2fma(b, w1, acc[r][1]);
            }
        }
    }
}

__device__ __forceinline__ int ring_next2(int cur) { return cur + 2 >= 3 ? cur - 1 : cur + 2; }
__device__ __forceinline__ int ring_adv(int cur)   { return cur == 2 ? 0 : cur + 1; }

// acc += in(own rows) @ W, W streamed via 3-buffer cp.async ring (depth 2).
__device__ __forceinline__ void gemm_run(const float* __restrict__ in,
                                         const float* __restrict__ W,
                                         F2 (&acc)[8][2], int r0, int c0, int t,
                                         float* ws) {
    __syncthreads();                       // protect ring vs previous gemm's readers
    stage_chunk(ws, W, 0, t);            cp_commit();
    stage_chunk(ws + CHF, W, 1, t);      cp_commit();
    int cur = 0;
    for (int ch = 0; ch < NCHK; ++ch) {
        cp_wait1();
        __syncthreads();
        if (ch + 2 < NCHK) stage_chunk(ws + ring_next2(cur) * CHF, W, ch + 2, t);
        cp_commit();                       // empty tail group keeps wait depth valid
        chunk_fma(in, ws + cur * CHF, acc, r0, c0, ch * KCH);
        cur = ring_adv(cur);
    }
}

// Dual-WEIGHT GEMM sharing activation loads: accA += in@Wa ; accB += in@Wb.
__device__ __forceinline__ void gemm_dual(const float* __restrict__ in,
                                          const float* __restrict__ Wa,
                                          const float* __restrict__ Wb,
                                          F2 (&accA)[8][2], F2 (&accB)[8][2],
                                          int r0, int c0, int t,
                                          float* wsA, float* wsB) {
    __syncthreads();
    stage_chunk(wsA, Wa, 0, t); stage_chunk(wsB, Wb, 0, t); cp_commit();
    stage_chunk(wsA + CHF, Wa, 1, t); stage_chunk(wsB + CHF, Wb, 1, t); cp_commit();
    int cur = 0;
    for (int ch = 0; ch < NCHK; ++ch) {
        cp_wait1();
        __syncthreads();
        if (ch + 2 < NCHK) {
            stage_chunk(wsA + ring_next2(cur) * CHF, Wa, ch + 2, t);
            stage_chunk(wsB + ring_next2(cur) * CHF, Wb, ch + 2, t);
        }
        cp_commit();
        const float* wa = wsA + cur * CHF;
        const float* wbp = wsB + cur * CHF;
        const int kb = ch * KCH;
#pragma unroll
        for (int kk = 0; kk < KCH; kk += 4) {
            float4 a[8];
#pragma unroll
            for (int r = 0; r < 8; ++r)
                a[r] = *reinterpret_cast<const float4*>(in + (r0 + r) * H + kb + kk);
#pragma unroll
            for (int k = 0; k < 4; ++k) {
                float4 wva = *reinterpret_cast<const float4*>(wa + (kk + k) * H + c0);
                float4 wvb = *reinterpret_cast<const float4*>(wbp + (kk + k) * H + c0);
                F2 wa0 = f2mk(wva.x, wva.y), wa1 = f2mk(wva.z, wva.w);
                F2 wb0 = f2mk(wvb.x, wvb.y), wb1 = f2mk(wvb.z, wvb.w);
#pragma unroll
                for (int r = 0; r < 8; ++r) {
                    F2 b = f2bcast(f4c(a[r], k));
                    accA[r][0] = f2fma(b, wa0, accA[r][0]);
                    accA[r][1] = f2fma(b, wa1, accA[r][1]);
                    accB[r][0] = f2fma(b, wb0, accB[r][0]);
                    accB[r][1] = f2fma(b, wb1, accB[r][1]);
                }
            }
        }
        cur = ring_adv(cur);
    }
}

// Dual-INPUT fused GEMM, single accumulator: acc += inA@Wa + inB@Wb.
// Register peak ~= single gemm_run (the two chunk_fma calls are sequential,
// reusing the same activation registers).
__device__ __forceinline__ void gemm_dual_in(const float* __restrict__ inA,
                                             const float* __restrict__ Wa,
                                             const float* __restrict__ inB,
                                             const float* __restrict__ Wb,
                                             F2 (&acc)[8][2],
                                             int r0, int c0, int t,
                                             float* wsA, float* wsB) {
    __syncthreads();
    stage_chunk(wsA, Wa, 0, t); stage_chunk(wsB, Wb, 0, t); cp_commit();
    stage_chunk(wsA + CHF, Wa, 1, t); stage_chunk(wsB + CHF, Wb, 1, t); cp_commit();
    int cur = 0;
    for (int ch = 0; ch < NCHK; ++ch) {
        cp_wait1();
        __syncthreads();
        if (ch + 2 < NCHK) {
            stage_chunk(wsA + ring_next2(cur) * CHF, Wa, ch + 2, t);
            stage_chunk(wsB + ring_next2(cur) * CHF, Wb, ch + 2, t);
        }
        cp_commit();
        chunk_fma(inA, wsA + cur * CHF, acc, r0, c0, ch * KCH);
        chunk_fma(inB, wsB + cur * CHF, acc, r0, c0, ch * KCH);
        cur = ring_adv(cur);
    }
}

__device__ __forceinline__ void acc_zero(F2 (&acc)[8][2]) {
#pragma unroll
    for (int r = 0; r < 8; ++r) { acc[r][0] = f2mk(0.f, 0.f); acc[r][1] = f2mk(0.f, 0.f); }
}
__device__ __forceinline__ void acc_bias(F2 (&acc)[8][2], const float* __restrict__ bias,
                                         int c0, float s) {
    float4 b = *reinterpret_cast<const float4*>(bias + c0);
#pragma unroll
    for (int r = 0; r < 8; ++r) {
        acc[r][0] = f2mk(b.x * s, b.y * s);
        acc[r][1] = f2mk(b.z * s, b.w * s);
    }
}
__device__ __forceinline__ void acc_from_smem(F2 (&acc)[8][2], const float* __restrict__ src,
                                              int r0, int c0) {
#pragma unroll
    for (int r = 0; r < 8; ++r) {
        float4 v = *reinterpret_cast<const float4*>(src + (r0 + r) * H + c0);
        acc[r][0] = f2mk(v.x, v.y);
        acc[r][1] = f2mk(v.z, v.w);
    }
}
__device__ __forceinline__ void acc_store(float* __restrict__ out, F2 (&acc)[8][2],
                                          int r0, int c0, bool relu) {
#pragma unroll
    for (int r = 0; r < 8; ++r) {
        float4 v = make_float4(acc[r][0].f.x, acc[r][0].f.y, acc[r][1].f.x, acc[r][1].f.y);
        if (relu) {
            v.x = fmaxf(v.x, 0.f); v.y = fmaxf(v.y, 0.f);
            v.z = fmaxf(v.z, 0.f); v.w = fmaxf(v.w, 0.f);
        }
        *reinterpret_cast<float4*>(out + (r0 + r) * H + c0) = v;
    }
}

__global__ void __launch_bounds__(THREADS)
rrn_kernel(const int* __restrict__ sources, const int* __restrict__ targets,
           const int* __restrict__ types, const int* __restrict__ diffs,
           const int* __restrict__ question,
           const float* __restrict__ pre_w1, const float* __restrict__ pre_b1,
           const float* __restrict__ pre_w2, const float* __restrict__ pre_b2,
           const float* __restrict__ msg_w1, const float* __restrict__ msg_b1,
           const float* __restrict__ msg_w2, const float* __restrict__ msg_b2,
           const float* __restrict__ node_w1, const float* __restrict__ node_b1,
           const float* __restrict__ node_w2, const float* __restrict__ node_b2,
           const float* __restrict__ out_w1, const float* __restrict__ out_b1,
           const float* __restrict__ out_w2, const float* __restrict__ out_b2,
           float* __restrict__ out)
{
    extern __shared__ float sm[];
    float* sh_h  = sm;                    // h (current hidden state)
    float* sh_xw = sm + 4096;             // x @ node_w1[0:128] + node_b1 (precomputed)
    float* sh_S  = sm + 8192;             // scratch: feats / S / m_agg / hidden / pooled
    float* wsA   = sm + 12288;            // cp.async W ring: 2 streams x 3 bufs x 4KB
    float* wsB   = wsA + 3 * CHF;

    const int t    = threadIdx.x;
    const int cta  = blockIdx.x;
    const int warp = t >> 5;              // == graph within CTA
    const int r0   = warp * 8;
    const int c0   = (t & 31) * 4;

    // ---- pre-MLP hidden = relu(one-hot gather of pre_w1 rows + b1) -> sh_S
    {
        const float b1 = pre_b1[t];
        for (int m = 0; m < MROWS; ++m) {
            const int node = cta * MROWS + m;
            const int b  = node >> 3;
            const int s  = sources[node];
            const int tg = targets[node];
            const int ty = types[node];
            const int d  = diffs[node];
            const int q  = question[b];
            float v = pre_w1[s * H + t] + pre_w1[(8 + tg) * H + t]
                    + pre_w1[(16 + ty) * H + t] + pre_w1[(19 + d) * H + t]
                    + pre_w1[(119 + q) * H + t] + b1;
            sh_S[m * H + t] = fmaxf(v, 0.f);
        }
    }
    __syncthreads();

    // ---- x = hidden @ pre_w2 + pre_b2 -> sh_h  (h0 = x)
    {
        F2 acc[8][2];
        acc_bias(acc, pre_b2, c0, 1.0f);
        gemm_run(sh_S, pre_w2, acc, r0, c0, t, wsA);
        acc_store(sh_h, acc, r0, c0, false);
        __syncwarp();
    }

    // ---- xw = x @ node_w1[0:128] + node_b1 -> sh_xw  (step-invariant)
    {
        F2 acc[8][2];
        acc_bias(acc, node_b1, c0, 1.0f);
        gemm_run(sh_h, node_w1, acc, r0, c0, t, wsA);
        acc_store(sh_xw, acc, r0, c0, false);
        __syncwarp();
    }

    const float4 b1v = *reinterpret_cast<const float4*>(msg_b1 + c0);
    const float bias1[4] = {b1v.x, b1v.y, b1v.z, b1v.w};

    for (int step = 0; step < NSTEPS; ++step) {
        // A = h @ msg_w1[0:128] ; B = h @ msg_w1[128:256]  (both reg-resident)
        F2 accA[8][2], accB[8][2];
        acc_zero(accA); acc_zero(accB);
        gemm_dual(sh_h, msg_w1, msg_w1 + 128 * H, accA, accB, r0, c0, t, wsA, wsB);

        // S_i = sum_{j != i} relu(A_i + B_j + b1)  (in registers, into accA)
        {
#pragma unroll
            for (int cc = 0; cc < 4; ++cc) {
                const int p = cc >> 1, hl = cc & 1;
                float A[8], Bv[8];
#pragma unroll
                for (int r = 0; r < 8; ++r) {
                    A[r]  = hl ? accA[r][p].f.y : accA[r][p].f.x;
                    Bv[r] = hl ? accB[r][p].f.y : accB[r][p].f.x;
                }
                const float bc = bias1[cc];
#pragma unroll
                for (int i = 0; i < 8; ++i) {
                    float s = 0.f;
#pragma unroll
                    for (int j = 0; j < 8; ++j) s += fmaxf(A[i] + Bv[j] + bc, 0.f);
                    s -= fmaxf(A[i] + Bv[i] + bc, 0.f);    // drop self-edge
                    if (hl) accA[i][p].f.y = s; else accA[i][p].f.x = s;
                }
            }
            acc_store(sh_S, accA, r0, c0, false);          // S -> own slots
            __syncwarp();
        }

        // m_agg = S @ msg_w2 + 7*msg_b2 -> sh_S (own slots)
        {
            F2 acc[8][2];
            acc_bias(acc, msg_b2, c0, 7.0f);
            gemm_run(sh_S, msg_w2, acc, r0, c0, t, wsA);
            acc_store(sh_S, acc, r0, c0, false);
            __syncwarp();
        }

        // hidden = relu(xw + h@Wn1b + m_agg@Wn1c) -> sh_S  (FUSED dual-input pass)
        {
            F2 acc[8][2];
            acc_from_smem(acc, sh_xw, r0, c0);
            gemm_dual_in(sh_h, node_w1 + 128 * H, sh_S, node_w1 + 256 * H,
                         acc, r0, c0, t, wsA, wsB);
            acc_store(sh_S, acc, r0, c0, true);
            __syncwarp();
        }

        // h_new = hidden @ node_w2 + node_b2 -> sh_h ; pooled from regs
        {
            F2 acc[8][2];
            acc_bias(acc, node_b2, c0, 1.0f);
            gemm_run(sh_S, node_w2, acc, r0, c0, t, wsA);
            acc_store(sh_h, acc, r0, c0, false);
            float4 pool = make_float4(0.f, 0.f, 0.f, 0.f);
#pragma unroll
            for (int r = 0; r < 8; ++r) {
                pool.x += acc[r][0].f.x; pool.y += acc[r][0].f.y;
                pool.z += acc[r][1].f.x; pool.w += acc[r][1].f.y;
            }
            __syncthreads();               // all warps done reading sh_S rows
            *reinterpret_cast<float4*>(sh_S + warp * H + c0) = pool;  // row g = graph g
        }
        __syncthreads();

        // out hidden = relu(pooled @ out_w1 + out_b1) -> sh_S rows 4..7
        {
            float acc[NG];
            const float ob = out_b1[t];
#pragma unroll
            for (int g = 0; g < NG; ++g) acc[g] = ob;
#pragma unroll 8
            for (int k = 0; k < H; ++k) {
                const float w = out_w1[k * H + t];
#pragma unroll
                for (int g = 0; g < NG; ++g) acc[g] += sh_S[g * H + k] * w;
            }
#pragma unroll
            for (int g = 0; g < NG; ++g) sh_S[(4 + g) * H + t] = fmaxf(acc[g], 0.f);
        }
        __syncthreads();

        // logits = oh @ out_w2 + out_b2 -> gmem [step][bs][100]
        if (t < 100) {
            float acc[NG];
            const float ob = out_b2[t];
#pragma unroll
            for (int g = 0; g < NG; ++g) acc[g] = ob;
#pragma unroll 8
            for (int k = 0; k < H; ++k) {
                const float w = out_w2[k * 100 + t];
#pragma unroll
                for (int g = 0; g < NG; ++g) acc[g] += sh_S[(4 + g) * H + k] * w;
            }
#pragma unroll
            for (int g = 0; g < NG; ++g)
                out[(step * BS + cta * NG + g) * 100 + t] = acc[g];
        }
        // next iteration's gemm_dual begins with its entry __syncthreads
    }
}

extern "C" void kernel_launch(void* const* d_in, const int* in_sizes, int n_in,
                              void* d_out, int out_size) {
    (void)in_sizes; (void)n_in; (void)out_size;
    const int*   sources  = (const int*)  d_in[0];
    const int*   targets  = (const int*)  d_in[1];
    const int*   types    = (const int*)  d_in[2];
    const int*   diffs    = (const int*)  d_in[3];
    const int*   question = (const int*)  d_in[4];
    const float* pre_w1   = (const float*)d_in[5];
    const float* pre_b1   = (const float*)d_in[6];
    const float* pre_w2   = (const float*)d_in[7];
    const float* pre_b2   = (const float*)d_in[8];
    const float* msg_w1   = (const float*)d_in[9];
    const float* msg_b1   = (const float*)d_in[10];
    const float* msg_w2   = (const float*)d_in[11];
    const float* msg_b2   = (const float*)d_in[12];
    const float* node_w1  = (const float*)d_in[13];
    const float* node_b1  = (const float*)d_in[14];
    const float* node_w2  = (const float*)d_in[15];
    const float* node_b2  = (const float*)d_in[16];
    const float* out_w1   = (const float*)d_in[17];
    const float* out_b1   = (const float*)d_in[18];
    const float* out_w2   = (const float*)d_in[19];
    const float* out_b2   = (const float*)d_in[20];

    const size_t smem = (3 * 4096 + 6 * CHF) * sizeof(float);  // 48KB + 24KB = 72KB
    cudaFuncSetAttribute(rrn_kernel, cudaFuncAttributeMaxDynamicSharedMemorySize,
                         (int)smem);

    rrn_kernel<<<BS / NG, THREADS, smem>>>(
        sources, targets, types, diffs, question,
        pre_w1, pre_b1, pre_w2, pre_b2,
        msg_w1, msg_b1, msg_w2, msg_b2,
        node_w1, node_b1, node_w2, node_b2,
        out_w1, out_b1, out_w2, out_b2,
        (float*)d_out);
}

// round 14
// speedup vs baseline: 1.5635x; 1.1539x over previous
#include <cuda_runtime.h>
#include <cstdint>

// ---------------------------------------------------------------------------
// Fully-fused recurrent relational network, v10 = v9 + weight pre-composition:
//   m_agg @ Wn1c  ==  S @ (msg_w2 @ Wn1c) + 7*(msg_b2 @ Wn1c)
// A tiny prep kernel computes W_sc = msg_w2@Wn1c and b_sc = 7*msg_b2@Wn1c into
// __device__ scratch once per launch; the per-step m_agg GEMM disappears
// (6 -> 5 GEMMs, 4 -> 3 ring passes per step). b_sc folds into xw.
// Everything else identical to v9 (proven 756us): per-GEMM cp.async rings,
// dual A/B GEMM, dual-input node GEMM, xw in smem, 72KB smem, 3 CTAs/SM.
// ---------------------------------------------------------------------------

#define THREADS 128
#define NG      4
#define MROWS   32
#define BS      2048
#define NSTEPS  8
#define H       128
#define KCH     8                       // k-rows per staged chunk
#define NCHK    (H / KCH)               // 16 chunks per GEMM
#define CHF     (KCH * H)               // 1024 floats = 4KB per chunk

__device__ float g_wsc[H * H];          // msg_w2 @ node_w1[256:384]  (64KB)
__device__ float g_bsc[H];              // 7 * msg_b2 @ node_w1[256:384]

union F2 { float2 f; unsigned long long u; };

__device__ __forceinline__ F2 f2fma(F2 a, F2 b, F2 c) {
    F2 d;
    asm("fma.rn.f32x2 %0, %1, %2, %3;" : "=l"(d.u) : "l"(a.u), "l"(b.u), "l"(c.u));
    return d;
}
__device__ __forceinline__ F2 f2bcast(float x) {
    F2 r; unsigned xi = __float_as_uint(x);
    asm("mov.b64 %0, {%1, %1};" : "=l"(r.u) : "r"(xi));
    return r;
}
__device__ __forceinline__ F2 f2mk(float x, float y) { F2 r; r.f.x = x; r.f.y = y; return r; }

__device__ __forceinline__ void cp_commit() { asm volatile("cp.async.commit_group;" ::: "memory"); }
__device__ __forceinline__ void cp_wait1()  { asm volatile("cp.async.wait_group 1;"  ::: "memory"); }

__device__ __forceinline__ float f4c(const float4& v, int k) {
    return k == 0 ? v.x : k == 1 ? v.y : k == 2 ? v.z : v.w;
}

// ---- prep kernel: W_sc = msg_w2 @ Wn1c ; b_sc = 7 * msg_b2 @ Wn1c ---------
__global__ void __launch_bounds__(THREADS)
prep_kernel(const float* __restrict__ msg_w2, const float* __restrict__ msg_b2,
            const float* __restrict__ node_w1c) {
    const int i = blockIdx.x;      // output row (k-index of S)
    const int j = threadIdx.x;     // output column
    float s = 0.f;
    for (int m = 0; m < H; ++m)
        s += msg_w2[i * H + m] * node_w1c[m * H + j];
    g_wsc[i * H + j] = s;
    if (i == 0) {
        float b = 0.f;
        for (int m = 0; m < H; ++m)
            b += msg_b2[m] * node_w1c[m * H + j];
        g_bsc[j] = 7.f * b;
    }
}

// Stage one 8x128 chunk (4KB): 256 float4, 2 per thread, coalesced.
__device__ __forceinline__ void stage_chunk(float* ws, const float* __restrict__ W,
                                            int chunk, int t) {
    const float4* src = reinterpret_cast<const float4*>(W + chunk * CHF) + t;
    unsigned dst = (unsigned)__cvta_generic_to_shared(ws) + t * 16;
#pragma unroll
    for (int i = 0; i < 2; ++i) {
        asm volatile("cp.async.cg.shared.global [%0], [%1], 16;"
                     :: "r"(dst + i * 2048), "l"(src + i * 128) : "memory");
    }
}

__device__ __forceinline__ void chunk_fma(const float* __restrict__ in,
                                          const float* __restrict__ wb,
                                          F2 (&acc)[8][2], int r0, int c0, int kb) {
#pragma unroll
    for (int kk = 0; kk < KCH; kk += 4) {
        float4 a[8];
#pragma unroll
        for (int r = 0; r < 8; ++r)
            a[r] = *reinterpret_cast<const float4*>(in + (r0 + r) * H + kb + kk);
#pragma unroll
        for (int k = 0; k < 4; ++k) {
            float4 wv = *reinterpret_cast<const float4*>(wb + (kk + k) * H + c0);
            F2 w0 = f2mk(wv.x, wv.y), w1 = f2mk(wv.z, wv.w);
#pragma unroll
            for (int r = 0; r < 8; ++r) {
                F2 b = f2bcast(f4c(a[r], k));
                acc[r][0] = f2fma(b, w0, acc[r][0]);
                acc[r][1] = f2fma(b, w1, acc[r][1]);
            }
        }
    }
}

__device__ __forceinline__ int ring_next2(int cur) { return cur + 2 >= 3 ? cur - 1 : cur + 2; }
__device__ __forceinline__ int ring_adv(int cur)   { return cur == 2 ? 0 : cur + 1; }

// acc += in(own rows) @ W, W streamed via 3-buffer cp.async ring (depth 2).
__device__ __forceinline__ void gemm_run(const float* __restrict__ in,
                                         const float* __restrict__ W,
                                         F2 (&acc)[8][2], int r0, int c0, int t,
                                         float* ws) {
    __syncthreads();                       // protect ring vs previous gemm's readers
    stage_chunk(ws, W, 0, t);            cp_commit();
    stage_chunk(ws + CHF, W, 1, t);      cp_commit();
    int cur = 0;
    for (int ch = 0; ch < NCHK; ++ch) {
        cp_wait1();
        __syncthreads();
        if (ch + 2 < NCHK) stage_chunk(ws + ring_next2(cur) * CHF, W, ch + 2, t);
        cp_commit();                       // empty tail group keeps wait depth valid
        chunk_fma(in, ws + cur * CHF, acc, r0, c0, ch * KCH);
        cur = ring_adv(cur);
    }
}

// Dual-WEIGHT GEMM sharing activation loads: accA += in@Wa ; accB += in@Wb.
__device__ __forceinline__ void gemm_dual(const float* __restrict__ in,
                                          const float* __restrict__ Wa,
                                          const float* __restrict__ Wb,
                                          F2 (&accA)[8][2], F2 (&accB)[8][2],
                                          int r0, int c0, int t,
                                          float* wsA, float* wsB) {
    __syncthreads();
    stage_chunk(wsA, Wa, 0, t); stage_chunk(wsB, Wb, 0, t); cp_commit();
    stage_chunk(wsA + CHF, Wa, 1, t); stage_chunk(wsB + CHF, Wb, 1, t); cp_commit();
    int cur = 0;
    for (int ch = 0; ch < NCHK; ++ch) {
        cp_wait1();
        __syncthreads();
        if (ch + 2 < NCHK) {
            stage_chunk(wsA + ring_next2(cur) * CHF, Wa, ch + 2, t);
            stage_chunk(wsB + ring_next2(cur) * CHF, Wb, ch + 2, t);
        }
        cp_commit();
        const float* wa = wsA + cur * CHF;
        const float* wbp = wsB + cur * CHF;
        const int kb = ch * KCH;
#pragma unroll
        for (int kk = 0; kk < KCH; kk += 4) {
            float4 a[8];
#pragma unroll
            for (int r = 0; r < 8; ++r)
                a[r] = *reinterpret_cast<const float4*>(in + (r0 + r) * H + kb + kk);
#pragma unroll
            for (int k = 0; k < 4; ++k) {
                float4 wva = *reinterpret_cast<const float4*>(wa + (kk + k) * H + c0);
                float4 wvb = *reinterpret_cast<const float4*>(wbp + (kk + k) * H + c0);
                F2 wa0 = f2mk(wva.x, wva.y), wa1 = f2mk(wva.z, wva.w);
                F2 wb0 = f2mk(wvb.x, wvb.y), wb1 = f2mk(wvb.z, wvb.w);
#pragma unroll
                for (int r = 0; r < 8; ++r) {
                    F2 b = f2bcast(f4c(a[r], k));
                    accA[r][0] = f2fma(b, wa0, accA[r][0]);
                    accA[r][1] = f2fma(b, wa1, accA[r][1]);
                    accB[r][0] = f2fma(b, wb0, accB[r][0]);
                    accB[r][1] = f2fma(b, wb1, accB[r][1]);
                }
            }
        }
        cur = ring_adv(cur);
    }
}

// Dual-INPUT fused GEMM, single accumulator: acc += inA@Wa + inB@Wb.
__device__ __forceinline__ void gemm_dual_in(const float* __restrict__ inA,
                                             const float* __restrict__ Wa,
                                             const float* __restrict__ inB,
                                             const float* __restrict__ Wb,
                                             F2 (&acc)[8][2],
                                             int r0, int c0, int t,
                                             float* wsA, float* wsB) {
    __syncthreads();
    stage_chunk(wsA, Wa, 0, t); stage_chunk(wsB, Wb, 0, t); cp_commit();
    stage_chunk(wsA + CHF, Wa, 1, t); stage_chunk(wsB + CHF, Wb, 1, t); cp_commit();
    int cur = 0;
    for (int ch = 0; ch < NCHK; ++ch) {
        cp_wait1();
        __syncthreads();
        if (ch + 2 < NCHK) {
            stage_chunk(wsA + ring_next2(cur) * CHF, Wa, ch + 2, t);
            stage_chunk(wsB + ring_next2(cur) * CHF, Wb, ch + 2, t);
        }
        cp_commit();
        chunk_fma(inA, wsA + cur * CHF, acc, r0, c0, ch * KCH);
        chunk_fma(inB, wsB + cur * CHF, acc, r0, c0, ch * KCH);
        cur = ring_adv(cur);
    }
}

__device__ __forceinline__ void acc_zero(F2 (&acc)[8][2]) {
#pragma unroll
    for (int r = 0; r < 8; ++r) { acc[r][0] = f2mk(0.f, 0.f); acc[r][1] = f2mk(0.f, 0.f); }
}
__device__ __forceinline__ void acc_bias(F2 (&acc)[8][2], const float* __restrict__ bias,
                                         int c0, float s) {
    float4 b = *reinterpret_cast<const float4*>(bias + c0);
#pragma unroll
    for (int r = 0; r < 8; ++r) {
        acc[r][0] = f2mk(b.x * s, b.y * s);
        acc[r][1] = f2mk(b.z * s, b.w * s);
    }
}
__device__ __forceinline__ void acc_from_smem(F2 (&acc)[8][2], const float* __restrict__ src,
                                              int r0, int c0) {
#pragma unroll
    for (int r = 0; r < 8; ++r) {
        float4 v = *reinterpret_cast<const float4*>(src + (r0 + r) * H + c0);
        acc[r][0] = f2mk(v.x, v.y);
        acc[r][1] = f2mk(v.z, v.w);
    }
}
__device__ __forceinline__ void acc_store(float* __restrict__ out, F2 (&acc)[8][2],
                                          int r0, int c0, bool relu) {
#pragma unroll
    for (int r = 0; r < 8; ++r) {
        float4 v = make_float4(acc[r][0].f.x, acc[r][0].f.y, acc[r][1].f.x, acc[r][1].f.y);
        if (relu) {
            v.x = fmaxf(v.x, 0.f); v.y = fmaxf(v.y, 0.f);
            v.z = fmaxf(v.z, 0.f); v.w = fmaxf(v.w, 0.f);
        }
        *reinterpret_cast<float4*>(out + (r0 + r) * H + c0) = v;
    }
}

__global__ void __launch_bounds__(THREADS)
rrn_kernel(const int* __restrict__ sources, const int* __restrict__ targets,
           const int* __restrict__ types, const int* __restrict__ diffs,
           const int* __restrict__ question,
           const float* __restrict__ pre_w1, const float* __restrict__ pre_b1,
           const float* __restrict__ pre_w2, const float* __restrict__ pre_b2,
           const float* __restrict__ msg_w1, const float* __restrict__ msg_b1,
           const float* __restrict__ node_w1, const float* __restrict__ node_b1,
           const float* __restrict__ node_w2, const float* __restrict__ node_b2,
           const float* __restrict__ out_w1, const float* __restrict__ out_b1,
           const float* __restrict__ out_w2, const float* __restrict__ out_b2,
           float* __restrict__ out)
{
    extern __shared__ float sm[];
    float* sh_h  = sm;                    // h (current hidden state)
    float* sh_xw = sm + 4096;             // x@Wn1a + node_b1 + b_sc (step-invariant)
    float* sh_S  = sm + 8192;             // scratch: feats / S / hidden / pooled
    float* wsA   = sm + 12288;            // cp.async W ring: 2 streams x 3 bufs x 4KB
    float* wsB   = wsA + 3 * CHF;

    const int t    = threadIdx.x;
    const int cta  = blockIdx.x;
    const int warp = t >> 5;              // == graph within CTA
    const int r0   = warp * 8;
    const int c0   = (t & 31) * 4;

    // ---- pre-MLP hidden = relu(one-hot gather of pre_w1 rows + b1) -> sh_S
    {
        const float b1 = pre_b1[t];
        for (int m = 0; m < MROWS; ++m) {
            const int node = cta * MROWS + m;
            const int b  = node >> 3;
            const int s  = sources[node];
            const int tg = targets[node];
            const int ty = types[node];
            const int d  = diffs[node];
            const int q  = question[b];
            float v = pre_w1[s * H + t] + pre_w1[(8 + tg) * H + t]
                    + pre_w1[(16 + ty) * H + t] + pre_w1[(19 + d) * H + t]
                    + pre_w1[(119 + q) * H + t] + b1;
            sh_S[m * H + t] = fmaxf(v, 0.f);
        }
    }
    __syncthreads();

    // ---- x = hidden @ pre_w2 + pre_b2 -> sh_h  (h0 = x)
    {
        F2 acc[8][2];
        acc_bias(acc, pre_b2, c0, 1.0f);
        gemm_run(sh_S, pre_w2, acc, r0, c0, t, wsA);
        acc_store(sh_h, acc, r0, c0, false);
        __syncwarp();
    }

    // ---- xw = x @ node_w1[0:128] + node_b1 + b_sc -> sh_xw  (step-invariant)
    {
        F2 acc[8][2];
        float4 nb = *reinterpret_cast<const float4*>(node_b1 + c0);
        float4 bs = *reinterpret_cast<const float4*>(g_bsc + c0);
#pragma unroll
        for (int r = 0; r < 8; ++r) {
            acc[r][0] = f2mk(nb.x + bs.x, nb.y + bs.y);
            acc[r][1] = f2mk(nb.z + bs.z, nb.w + bs.w);
        }
        gemm_run(sh_h, node_w1, acc, r0, c0, t, wsA);
        acc_store(sh_xw, acc, r0, c0, false);
        __syncwarp();
    }

    const float4 b1v = *reinterpret_cast<const float4*>(msg_b1 + c0);
    const float bias1[4] = {b1v.x, b1v.y, b1v.z, b1v.w};

    for (int step = 0; step < NSTEPS; ++step) {
        // A = h @ msg_w1[0:128] ; B = h @ msg_w1[128:256]  (both reg-resident)
        F2 accA[8][2], accB[8][2];
        acc_zero(accA); acc_zero(accB);
        gemm_dual(sh_h, msg_w1, msg_w1 + 128 * H, accA, accB, r0, c0, t, wsA, wsB);

        // S_i = sum_{j != i} relu(A_i + B_j + b1)  (in registers, into accA)
        {
#pragma unroll
            for (int cc = 0; cc < 4; ++cc) {
                const int p = cc >> 1, hl = cc & 1;
                float A[8], Bv[8];
#pragma unroll
                for (int r = 0; r < 8; ++r) {
                    A[r]  = hl ? accA[r][p].f.y : accA[r][p].f.x;
                    Bv[r] = hl ? accB[r][p].f.y : accB[r][p].f.x;
                }
                const float bc = bias1[cc];
#pragma unroll
                for (int i = 0; i < 8; ++i) {
                    float s = 0.f;
#pragma unroll
                    for (int j = 0; j < 8; ++j) s += fmaxf(A[i] + Bv[j] + bc, 0.f);
                    s -= fmaxf(A[i] + Bv[i] + bc, 0.f);    // drop self-edge
                    if (hl) accA[i][p].f.y = s; else accA[i][p].f.x = s;
                }
            }
            acc_store(sh_S, accA, r0, c0, false);          // S -> own slots
            __syncwarp();
        }

        // hidden = relu(xw + h@Wn1b + S@W_sc) -> sh_S  (m_agg GEMM folded away)
        {
            F2 acc[8][2];
            acc_from_smem(acc, sh_xw, r0, c0);
            gemm_dual_in(sh_h, node_w1 + 128 * H, sh_S, g_wsc,
                         acc, r0, c0, t, wsA, wsB);
            acc_store(sh_S, acc, r0, c0, true);
            __syncwarp();
        }

        // h_new = hidden @ node_w2 + node_b2 -> sh_h ; pooled from regs
        {
            F2 acc[8][2];
            acc_bias(acc, node_b2, c0, 1.0f);
            gemm_run(sh_S, node_w2, acc, r0, c0, t, wsA);
            acc_store(sh_h, acc, r0, c0, false);
            float4 pool = make_float4(0.f, 0.f, 0.f, 0.f);
#pragma unroll
            for (int r = 0; r < 8; ++r) {
                pool.x += acc[r][0].f.x; pool.y += acc[r][0].f.y;
                pool.z += acc[r][1].f.x; pool.w += acc[r][1].f.y;
            }
            __syncthreads();               // all warps done reading sh_S rows
            *reinterpret_cast<float4*>(sh_S + warp * H + c0) = pool;  // row g = graph g
        }
        __syncthreads();

        // out hidden = relu(pooled @ out_w1 + out_b1) -> sh_S rows 4..7
        {
            float acc[NG];
            const float ob = out_b1[t];
#pragma unroll
            for (int g = 0; g < NG; ++g) acc[g] = ob;
#pragma unroll 8
            for (int k = 0; k < H; ++k) {
                const float w = out_w1[k * H + t];
#pragma unroll
                for (int g = 0; g < NG; ++g) acc[g] += sh_S[g * H + k] * w;
            }
#pragma unroll
            for (int g = 0; g < NG; ++g) sh_S[(4 + g) * H + t] = fmaxf(acc[g], 0.f);
        }
        __syncthreads();

        // logits = oh @ out_w2 + out_b2 -> gmem [step][bs][100]
        if (t < 100) {
            float acc[NG];
            const float ob = out_b2[t];
#pragma unroll
            for (int g = 0; g < NG; ++g) acc[g] = ob;
#pragma unroll 8
            for (int k = 0; k < H; ++k) {
                const float w = out_w2[k * 100 + t];
#pragma unroll
                for (int g = 0; g < NG; ++g) acc[g] += sh_S[(4 + g) * H + k] * w;
            }
#pragma unroll
            for (int g = 0; g < NG; ++g)
                out[(step * BS + cta * NG + g) * 100 + t] = acc[g];
        }
        // next iteration's gemm_dual begins with its entry __syncthreads
    }
}

extern "C" void kernel_launch(void* const* d_in, const int* in_sizes, int n_in,
                              void* d_out, int out_size) {
    (void)in_sizes; (void)n_in; (void)out_size;
    const int*   sources  = (const int*)  d_in[0];
    const int*   targets  = (const int*)  d_in[1];
    const int*   types    = (const int*)  d_in[2];
    const int*   diffs    = (const int*)  d_in[3];
    const int*   question = (const int*)  d_in[4];
    const float* pre_w1   = (const float*)d_in[5];
    const float* pre_b1   = (const float*)d_in[6];
    const float* pre_w2   = (const float*)d_in[7];
    const float* pre_b2   = (const float*)d_in[8];
    const float* msg_w1   = (const float*)d_in[9];
    const float* msg_b1   = (const float*)d_in[10];
    const float* msg_w2   = (const float*)d_in[11];
    const float* msg_b2   = (const float*)d_in[12];
    const float* node_w1  = (const float*)d_in[13];
    const float* node_b1  = (const float*)d_in[14];
    const float* node_w2  = (const float*)d_in[15];
    const float* node_b2  = (const float*)d_in[16];
    const float* out_w1   = (const float*)d_in[17];
    const float* out_b1   = (const float*)d_in[18];
    const float* out_w2   = (const float*)d_in[19];
    const float* out_b2   = (const float*)d_in[20];

    // prep: W_sc = msg_w2 @ node_w1[256:384], b_sc = 7*msg_b2 @ node_w1[256:384]
    prep_kernel<<<H, THREADS>>>(msg_w2, msg_b2, node_w1 + 256 * H);

    const size_t smem = (3 * 4096 + 6 * CHF) * sizeof(float);  // 48KB + 24KB = 72KB
    cudaFuncSetAttribute(rrn_kernel, cudaFuncAttributeMaxDynamicSharedMemorySize,
                         (int)smem);

    rrn_kernel<<<BS / NG, THREADS, smem>>>(
        sources, targets, types, diffs, question,
        pre_w1, pre_b1, pre_w2, pre_b2,
        msg_w1, msg_b1,
        node_w1, node_b1, node_w2, node_b2,
        out_w1, out_b1, out_w2, out_b2,
        (float*)d_out);
}

// round 15
// speedup vs baseline: 1.6990x; 1.0866x over previous
#include <cuda_runtime.h>
#include <cstdint>

// ---------------------------------------------------------------------------
// Fully-fused recurrent relational network, v11 = v10 + node_w2 composition:
// carry hidden (pre-W2) as the recurrent state; h = hidden@W2+b2 is consumed
// only linearly, so W2 folds into the next step's weights:
//   W_ma = W2@msg_w1[0:128], W_mb = W2@msg_w1[128:256], W_nb = W2@node_w1b
//   bias_s = msg_b1 + b2@Wm1a + b2@Wm1b ;  b_nb = b2@Wn1b
//   pooled = (sum_n hidden)@W2 + 8*b2   (tiny 4-row transform, out-MLP style)
// The per-step 32-row h_new GEMM ring pass disappears: 3 ring passes -> 2.
// Step 0 consumes h_0 = x with the ORIGINAL weights (pointer ternary).
// Everything else identical to v10 (655us proven): per-GEMM cp.async rings,
// dual A/B GEMM, dual-input node GEMM, xw in smem, 72KB smem, 3 CTAs/SM.
// ---------------------------------------------------------------------------

#define THREADS 128
#define NG      4
#define MROWS   32
#define BS      2048
#define NSTEPS  8
#define H       128
#define KCH     8                       // k-rows per staged chunk
#define NCHK    (H / KCH)               // 16 chunks per GEMM
#define CHF     (KCH * H)               // 1024 floats = 4KB per chunk

__device__ float g_wsc[H * H];          // msg_w2 @ node_w1[256:384]
__device__ float g_wma[H * H];          // node_w2 @ msg_w1[0:128]
__device__ float g_wmb[H * H];          // node_w2 @ msg_w1[128:256]
__device__ float g_wnb[H * H];          // node_w2 @ node_w1[128:256]
__device__ float g_bsc[H];              // 7 * msg_b2 @ node_w1[256:384]
__device__ float g_biass[H];            // msg_b1 + node_b2@(Wm1a + Wm1b)
__device__ float g_bnb[H];              // node_b2 @ node_w1[128:256]

union F2 { float2 f; unsigned long long u; };

__device__ __forceinline__ F2 f2fma(F2 a, F2 b, F2 c) {
    F2 d;
    asm("fma.rn.f32x2 %0, %1, %2, %3;" : "=l"(d.u) : "l"(a.u), "l"(b.u), "l"(c.u));
    return d;
}
__device__ __forceinline__ F2 f2bcast(float x) {
    F2 r; unsigned xi = __float_as_uint(x);
    asm("mov.b64 %0, {%1, %1};" : "=l"(r.u) : "r"(xi));
    return r;
}
__device__ __forceinline__ F2 f2mk(float x, float y) { F2 r; r.f.x = x; r.f.y = y; return r; }

__device__ __forceinline__ void cp_commit() { asm volatile("cp.async.commit_group;" ::: "memory"); }
__device__ __forceinline__ void cp_wait1()  { asm volatile("cp.async.wait_group 1;"  ::: "memory"); }

__device__ __forceinline__ float f4c(const float4& v, int k) {
    return k == 0 ? v.x : k == 1 ? v.y : k == 2 ? v.z : v.w;
}

// ---- prep kernel: composed weights + bias vectors (once per launch) -------
// grid (H, 4): y selects the product, x = output row i, thread = column j.
__global__ void __launch_bounds__(THREADS)
prep_kernel(const float* __restrict__ msg_w1, const float* __restrict__ msg_b1,
            const float* __restrict__ msg_w2, const float* __restrict__ msg_b2,
            const float* __restrict__ node_w1, const float* __restrict__ node_b2,
            const float* __restrict__ node_w2) {
    const int i = blockIdx.x;
    const int j = threadIdx.x;
    const int which = blockIdx.y;
    const float* L; const float* R; float* O;
    if (which == 0)      { L = msg_w2;  R = node_w1 + 256 * H; O = g_wsc; }
    else if (which == 1) { L = node_w2; R = msg_w1;            O = g_wma; }
    else if (which == 2) { L = node_w2; R = msg_w1 + 128 * H;  O = g_wmb; }
    else                 { L = node_w2; R = node_w1 + 128 * H; O = g_wnb; }
    float s = 0.f;
    for (int m = 0; m < H; ++m) s += L[i * H + m] * R[m * H + j];
    O[i * H + j] = s;
    if (i == 0) {
        if (which == 0) {
            float b = 0.f;
            for (int m = 0; m < H; ++m) b += msg_b2[m] * (node_w1 + 256 * H)[m * H + j];
            g_bsc[j] = 7.f * b;
        } else if (which == 1) {
            float b = 0.f;
            for (int m = 0; m < H; ++m)
                b += node_b2[m] * (msg_w1[m * H + j] + (msg_w1 + 128 * H)[m * H + j]);
            g_biass[j] = msg_b1[j] + b;
        } else if (which == 3) {
            float b = 0.f;
            for (int m = 0; m < H; ++m) b += node_b2[m] * (node_w1 + 128 * H)[m * H + j];
            g_bnb[j] = b;
        }
    }
}

// Stage one 8x128 chunk (4KB): 256 float4, 2 per thread, coalesced.
__device__ __forceinline__ void stage_chunk(float* ws, const float* __restrict__ W,
                                            int chunk, int t) {
    const float4* src = reinterpret_cast<const float4*>(W + chunk * CHF) + t;
    unsigned dst = (unsigned)__cvta_generic_to_shared(ws) + t * 16;
#pragma unroll
    for (int i = 0; i < 2; ++i) {
        asm volatile("cp.async.cg.shared.global [%0], [%1], 16;"
                     :: "r"(dst + i * 2048), "l"(src + i * 128) : "memory");
    }
}

__device__ __forceinline__ void chunk_fma(const float* __restrict__ in,
                                          const float* __restrict__ wb,
                                          F2 (&acc)[8][2], int r0, int c0, int kb) {
#pragma unroll
    for (int kk = 0; kk < KCH; kk += 4) {
        float4 a[8];
#pragma unroll
        for (int r = 0; r < 8; ++r)
            a[r] = *reinterpret_cast<const float4*>(in + (r0 + r) * H + kb + kk);
#pragma unroll
        for (int k = 0; k < 4; ++k) {
            float4 wv = *reinterpret_cast<const float4*>(wb + (kk + k) * H + c0);
            F2 w0 = f2mk(wv.x, wv.y), w1 = f2mk(wv.z, wv.w);
#pragma unroll
            for (int r = 0; r < 8; ++r) {
                F2 b = f2bcast(f4c(a[r], k));
                acc[r][0] = f2fma(b, w0, acc[r][0]);
                acc[r][1] = f2fma(b, w1, acc[r][1]);
            }
        }
    }
}

__device__ __forceinline__ int ring_next2(int cur) { return cur + 2 >= 3 ? cur - 1 : cur + 2; }
__device__ __forceinline__ int ring_adv(int cur)   { return cur == 2 ? 0 : cur + 1; }

// acc += in(own rows) @ W, W streamed via 3-buffer cp.async ring (depth 2).
__device__ __forceinline__ void gemm_run(const float* __restrict__ in,
                                         const float* __restrict__ W,
                                         F2 (&acc)[8][2], int r0, int c0, int t,
                                         float* ws) {
    __syncthreads();
    stage_chunk(ws, W, 0, t);            cp_commit();
    stage_chunk(ws + CHF, W, 1, t);      cp_commit();
    int cur = 0;
    for (int ch = 0; ch < NCHK; ++ch) {
        cp_wait1();
        __syncthreads();
        if (ch + 2 < NCHK) stage_chunk(ws + ring_next2(cur) * CHF, W, ch + 2, t);
        cp_commit();
        chunk_fma(in, ws + cur * CHF, acc, r0, c0, ch * KCH);
        cur = ring_adv(cur);
    }
}

// Dual-WEIGHT GEMM sharing activation loads: accA += in@Wa ; accB += in@Wb.
__device__ __forceinline__ void gemm_dual(const float* __restrict__ in,
                                          const float* __restrict__ Wa,
                                          const float* __restrict__ Wb,
                                          F2 (&accA)[8][2], F2 (&accB)[8][2],
                                          int r0, int c0, int t,
                                          float* wsA, float* wsB) {
    __syncthreads();
    stage_chunk(wsA, Wa, 0, t); stage_chunk(wsB, Wb, 0, t); cp_commit();
    stage_chunk(wsA + CHF, Wa, 1, t); stage_chunk(wsB + CHF, Wb, 1, t); cp_commit();
    int cur = 0;
    for (int ch = 0; ch < NCHK; ++ch) {
        cp_wait1();
        __syncthreads();
        if (ch + 2 < NCHK) {
            stage_chunk(wsA + ring_next2(cur) * CHF, Wa, ch + 2, t);
            stage_chunk(wsB + ring_next2(cur) * CHF, Wb, ch + 2, t);
        }
        cp_commit();
        const float* wa = wsA + cur * CHF;
        const float* wbp = wsB + cur * CHF;
        const int kb = ch * KCH;
#pragma unroll
        for (int kk = 0; kk < KCH; kk += 4) {
            float4 a[8];
#pragma unroll
            for (int r = 0; r < 8; ++r)
                a[r] = *reinterpret_cast<const float4*>(in + (r0 + r) * H + kb + kk);
#pragma unroll
            for (int k = 0; k < 4; ++k) {
                float4 wva = *reinterpret_cast<const float4*>(wa + (kk + k) * H + c0);
                float4 wvb = *reinterpret_cast<const float4*>(wbp + (kk + k) * H + c0);
                F2 wa0 = f2mk(wva.x, wva.y), wa1 = f2mk(wva.z, wva.w);
                F2 wb0 = f2mk(wvb.x, wvb.y), wb1 = f2mk(wvb.z, wvb.w);
#pragma unroll
                for (int r = 0; r < 8; ++r) {
                    F2 b = f2bcast(f4c(a[r], k));
                    accA[r][0] = f2fma(b, wa0, accA[r][0]);
                    accA[r][1] = f2fma(b, wa1, accA[r][1]);
                    accB[r][0] = f2fma(b, wb0, accB[r][0]);
                    accB[r][1] = f2fma(b, wb1, accB[r][1]);
                }
            }
        }
        cur = ring_adv(cur);
    }
}

// Dual-INPUT fused GEMM, single accumulator: acc += inA@Wa + inB@Wb.
__device__ __forceinline__ void gemm_dual_in(const float* __restrict__ inA,
                                             const float* __restrict__ Wa,
                                             const float* __restrict__ inB,
                                             const float* __restrict__ Wb,
                                             F2 (&acc)[8][2],
                                             int r0, int c0, int t,
                                             float* wsA, float* wsB) {
    __syncthreads();
    stage_chunk(wsA, Wa, 0, t); stage_chunk(wsB, Wb, 0, t); cp_commit();
    stage_chunk(wsA + CHF, Wa, 1, t); stage_chunk(wsB + CHF, Wb, 1, t); cp_commit();
    int cur = 0;
    for (int ch = 0; ch < NCHK; ++ch) {
        cp_wait1();
        __syncthreads();
        if (ch + 2 < NCHK) {
            stage_chunk(wsA + ring_next2(cur) * CHF, Wa, ch + 2, t);
            stage_chunk(wsB + ring_next2(cur) * CHF, Wb, ch + 2, t);
        }
        cp_commit();
        chunk_fma(inA, wsA + cur * CHF, acc, r0, c0, ch * KCH);
        chunk_fma(inB, wsB + cur * CHF, acc, r0, c0, ch * KCH);
        cur = ring_adv(cur);
    }
}

__device__ __forceinline__ void acc_zero(F2 (&acc)[8][2]) {
#pragma unroll
    for (int r = 0; r < 8; ++r) { acc[r][0] = f2mk(0.f, 0.f); acc[r][1] = f2mk(0.f, 0.f); }
}
__device__ __forceinline__ void acc_bias(F2 (&acc)[8][2], const float* __restrict__ bias,
                                         int c0, float s) {
    float4 b = *reinterpret_cast<const float4*>(bias + c0);
#pragma unroll
    for (int r = 0; r < 8; ++r) {
        acc[r][0] = f2mk(b.x * s, b.y * s);
        acc[r][1] = f2mk(b.z * s, b.w * s);
    }
}
__device__ __forceinline__ void acc_from_smem(F2 (&acc)[8][2], const float* __restrict__ src,
                                              int r0, int c0) {
#pragma unroll
    for (int r = 0; r < 8; ++r) {
        float4 v = *reinterpret_cast<const float4*>(src + (r0 + r) * H + c0);
        acc[r][0] = f2mk(v.x, v.y);
        acc[r][1] = f2mk(v.z, v.w);
    }
}
__device__ __forceinline__ void acc_store(float* __restrict__ out, F2 (&acc)[8][2],
                                          int r0, int c0, bool relu) {
#pragma unroll
    for (int r = 0; r < 8; ++r) {
        float4 v = make_float4(acc[r][0].f.x, acc[r][0].f.y, acc[r][1].f.x, acc[r][1].f.y);
        if (relu) {
            v.x = fmaxf(v.x, 0.f); v.y = fmaxf(v.y, 0.f);
            v.z = fmaxf(v.z, 0.f); v.w = fmaxf(v.w, 0.f);
        }
        *reinterpret_cast<float4*>(out + (r0 + r) * H + c0) = v;
    }
}

__global__ void __launch_bounds__(THREADS)
rrn_kernel(const int* __restrict__ sources, const int* __restrict__ targets,
           const int* __restrict__ types, const int* __restrict__ diffs,
           const int* __restrict__ question,
           const float* __restrict__ pre_w1, const float* __restrict__ pre_b1,
           const float* __restrict__ pre_w2, const float* __restrict__ pre_b2,
           const float* __restrict__ msg_w1, const float* __restrict__ msg_b1,
           const float* __restrict__ node_w1, const float* __restrict__ node_b1,
           const float* __restrict__ node_w2, const float* __restrict__ node_b2,
           const float* __restrict__ out_w1, const float* __restrict__ out_b1,
           const float* __restrict__ out_w2, const float* __restrict__ out_b2,
           float* __restrict__ out)
{
    extern __shared__ float sm[];
    float* sh_h  = sm;                    // carried state: x (step0) then hidden_t
    float* sh_xw = sm + 4096;             // x@Wn1a + node_b1 + b_sc (step-invariant)
    float* sh_S  = sm + 8192;             // scratch: feats / S / poolh / pooled / oh
    float* wsA   = sm + 12288;            // cp.async W ring: 2 streams x 3 bufs x 4KB
    float* wsB   = wsA + 3 * CHF;

    const int t    = threadIdx.x;
    const int cta  = blockIdx.x;
    const int warp = t >> 5;              // == graph within CTA
    const int r0   = warp * 8;
    const int c0   = (t & 31) * 4;

    // ---- pre-MLP hidden = relu(one-hot gather of pre_w1 rows + b1) -> sh_S
    {
        const float b1 = pre_b1[t];
        for (int m = 0; m < MROWS; ++m) {
            const int node = cta * MROWS + m;
            const int b  = node >> 3;
            const int s  = sources[node];
            const int tg = targets[node];
            const int ty = types[node];
            const int d  = diffs[node];
            const int q  = question[b];
            float v = pre_w1[s * H + t] + pre_w1[(8 + tg) * H + t]
                    + pre_w1[(16 + ty) * H + t] + pre_w1[(19 + d) * H + t]
                    + pre_w1[(119 + q) * H + t] + b1;
            sh_S[m * H + t] = fmaxf(v, 0.f);
        }
    }
    __syncthreads();

    // ---- x = hidden @ pre_w2 + pre_b2 -> sh_h  (h0 = x)
    {
        F2 acc[8][2];
        acc_bias(acc, pre_b2, c0, 1.0f);
        gemm_run(sh_S, pre_w2, acc, r0, c0, t, wsA);
        acc_store(sh_h, acc, r0, c0, false);
        __syncwarp();
    }

    // ---- xw = x @ node_w1[0:128] + node_b1 + b_sc -> sh_xw  (step-invariant)
    {
        F2 acc[8][2];
        float4 nb = *reinterpret_cast<const float4*>(node_b1 + c0);
        float4 bs = *reinterpret_cast<const float4*>(g_bsc + c0);
#pragma unroll
        for (int r = 0; r < 8; ++r) {
            acc[r][0] = f2mk(nb.x + bs.x, nb.y + bs.y);
            acc[r][1] = f2mk(nb.z + bs.z, nb.w + bs.w);
        }
        gemm_run(sh_h, node_w1, acc, r0, c0, t, wsA);
        acc_store(sh_xw, acc, r0, c0, false);
        __syncwarp();
    }

    // S-phase biases: step0 uses msg_b1; steps>=1 use composed g_biass.
    const float4 b0v = *reinterpret_cast<const float4*>(msg_b1 + c0);
    const float4 bcv = *reinterpret_cast<const float4*>(g_biass + c0);
    const float bias0[4] = {b0v.x, b0v.y, b0v.z, b0v.w};
    const float biasc[4] = {bcv.x, bcv.y, bcv.z, bcv.w};

    for (int step = 0; step < NSTEPS; ++step) {
        const float* Wa = step ? g_wma : msg_w1;
        const float* Wb = step ? g_wmb : msg_w1 + 128 * H;
        const float* Wn = step ? g_wnb : node_w1 + 128 * H;

        // A/B parts (reg-resident); input sh_h = x or hidden_{t-1}
        F2 accA[8][2], accB[8][2];
        acc_zero(accA); acc_zero(accB);
        gemm_dual(sh_h, Wa, Wb, accA, accB, r0, c0, t, wsA, wsB);

        // S_i = sum_{j != i} relu(A_i + B_j + bias)  (into accA)
        {
#pragma unroll
            for (int cc = 0; cc < 4; ++cc) {
                const int p = cc >> 1, hl = cc & 1;
                float A[8], Bv[8];
#pragma unroll
                for (int r = 0; r < 8; ++r) {
                    A[r]  = hl ? accA[r][p].f.y : accA[r][p].f.x;
                    Bv[r] = hl ? accB[r][p].f.y : accB[r][p].f.x;
                }
                const float bc = step ? biasc[cc] : bias0[cc];
#pragma unroll
                for (int i = 0; i < 8; ++i) {
                    float s = 0.f;
#pragma unroll
                    for (int j = 0; j < 8; ++j) s += fmaxf(A[i] + Bv[j] + bc, 0.f);
                    s -= fmaxf(A[i] + Bv[i] + bc, 0.f);    // drop self-edge
                    if (hl) accA[i][p].f.y = s; else accA[i][p].f.x = s;
                }
            }
            acc_store(sh_S, accA, r0, c0, false);          // S -> own slots
            __syncwarp();
        }

        // hidden = relu(xw [+b_nb] + sh_h@Wn + S@W_sc) -> sh_h (in place: own rows)
        {
            F2 acc[8][2];
            acc_from_smem(acc, sh_xw, r0, c0);
            if (step) {
                float4 bn = *reinterpret_cast<const float4*>(g_bnb + c0);
#pragma unroll
                for (int r = 0; r < 8; ++r) {
                    acc[r][0].f.x += bn.x; acc[r][0].f.y += bn.y;
                    acc[r][1].f.x += bn.z; acc[r][1].f.y += bn.w;
                }
            }
            gemm_dual_in(sh_h, Wn, sh_S, g_wsc, acc, r0, c0, t, wsA, wsB);
            // relu + store hidden to sh_h (own rows; per-warp smem ops are ordered,
            // and cross-warp each warp touches only its own rows)
            acc_store(sh_h, acc, r0, c0, true);
            // poolh = sum over own graph's 8 rows of hidden (post-relu)
            float4 pool = make_float4(0.f, 0.f, 0.f, 0.f);
#pragma unroll
            for (int r = 0; r < 8; ++r) {
                pool.x += fmaxf(acc[r][0].f.x, 0.f); pool.y += fmaxf(acc[r][0].f.y, 0.f);
                pool.z += fmaxf(acc[r][1].f.x, 0.f); pool.w += fmaxf(acc[r][1].f.y, 0.f);
            }
            __syncthreads();               // all warps done reading sh_S (S matrix)
            *reinterpret_cast<float4*>(sh_S + warp * H + c0) = pool;  // row g = graph g
        }
        __syncthreads();

        // pooled = poolh @ node_w2 + 8*node_b2 -> sh_S rows 8..11
        {
            float acc[NG];
            const float nb = 8.f * node_b2[t];
#pragma unroll
            for (int g = 0; g < NG; ++g) acc[g] = nb;
#pragma unroll 8
            for (int k = 0; k < H; ++k) {
                const float w = node_w2[k * H + t];
#pragma unroll
                for (int g = 0; g < NG; ++g) acc[g] += sh_S[g * H + k] * w;
            }
#pragma unroll
            for (int g = 0; g < NG; ++g) sh_S[(8 + g) * H + t] = acc[g];
        }
        __syncthreads();

        // out hidden = relu(pooled @ out_w1 + out_b1) -> sh_S rows 4..7
        {
            float acc[NG];
            const float ob = out_b1[t];
#pragma unroll
            for (int g = 0; g < NG; ++g) acc[g] = ob;
#pragma unroll 8
            for (int k = 0; k < H; ++k) {
                const float w = out_w1[k * H + t];
#pragma unroll
                for (int g = 0; g < NG; ++g) acc[g] += sh_S[(8 + g) * H + k] * w;
            }
#pragma unroll
            for (int g = 0; g < NG; ++g) sh_S[(4 + g) * H + t] = fmaxf(acc[g], 0.f);
        }
        __syncthreads();

        // logits = oh @ out_w2 + out_b2 -> gmem [step][bs][100]
        if (t < 100) {
            float acc[NG];
            const float ob = out_b2[t];
#pragma unroll
            for (int g = 0; g < NG; ++g) acc[g] = ob;
#pragma unroll 8
            for (int k = 0; k < H; ++k) {
                const float w = out_w2[k * 100 + t];
#pragma unroll
                for (int g = 0; g < NG; ++g) acc[g] += sh_S[(4 + g) * H + k] * w;
            }
#pragma unroll
            for (int g = 0; g < NG; ++g)
                out[(step * BS + cta * NG + g) * 100 + t] = acc[g];
        }
        // next iteration's gemm_dual begins with its entry __syncthreads
    }
}

extern "C" void kernel_launch(void* const* d_in, const int* in_sizes, int n_in,
                              void* d_out, int out_size) {
    (void)in_sizes; (void)n_in; (void)out_size;
    const int*   sources  = (const int*)  d_in[0];
    const int*   targets  = (const int*)  d_in[1];
    const int*   types    = (const int*)  d_in[2];
    const int*   diffs    = (const int*)  d_in[3];
    const int*   question = (const int*)  d_in[4];
    const float* pre_w1   = (const float*)d_in[5];
    const float* pre_b1   = (const float*)d_in[6];
    const float* pre_w2   = (const float*)d_in[7];
    const float* pre_b2   = (const float*)d_in[8];
    const float* msg_w1   = (const float*)d_in[9];
    const float* msg_b1   = (const float*)d_in[10];
    const float* msg_w2   = (const float*)d_in[11];
    const float* msg_b2   = (const float*)d_in[12];
    const float* node_w1  = (const float*)d_in[13];
    const float* node_b1  = (const float*)d_in[14];
    const float* node_w2  = (const float*)d_in[15];
    const float* node_b2  = (const float*)d_in[16];
    const float* out_w1   = (const float*)d_in[17];
    const float* out_b1   = (const float*)d_in[18];
    const float* out_w2   = (const float*)d_in[19];
    const float* out_b2   = (const float*)d_in[20];

    // prep: composed weights W_sc/W_ma/W_mb/W_nb + bias vectors
    prep_kernel<<<dim3(H, 4), THREADS>>>(msg_w1, msg_b1, msg_w2, msg_b2,
                                         node_w1, node_b2, node_w2);

    const size_t smem = (3 * 4096 + 6 * CHF) * sizeof(float);  // 48KB + 24KB = 72KB
    cudaFuncSetAttribute(rrn_kernel, cudaFuncAttributeMaxDynamicSharedMemorySize,
                         (int)smem);

    rrn_kernel<<<BS / NG, THREADS, smem>>>(
        sources, targets, types, diffs, question,
        pre_w1, pre_b1, pre_w2, pre_b2,
        msg_w1, msg_b1,
        node_w1, node_b1, node_w2, node_b2,
        out_w1, out_b1, out_w2, out_b2,
        (float*)d_out);
}

// round 17
// speedup vs baseline: 1.8259x; 1.0747x over previous
#include <cuda_runtime.h>
#include <cstdint>

// ---------------------------------------------------------------------------
// Fully-fused recurrent relational network, v12b (re-bench of v12 after infra
// flake — source functionally identical).
// v12 = v11 + pooled composition:
//   pooled = poolh@node_w2 + 8*node_b2 feeds ONLY oh = relu(pooled@out_w1+b)
//   => W_pool = node_w2@out_w1 ; b_oh = 8*(node_b2@out_w1) + out_b1
//   => oh = relu(poolh @ W_pool + b_oh)   (3 serial tail phases -> 2)
// Carried state = hidden (pre-W2); W2 folded into next-step weights (v11):
//   W_ma = W2@Wm1a, W_mb = W2@Wm1b, W_nb = W2@Wn1b, W_sc = msg_w2@Wn1c
//   bias_s = msg_b1 + b2@(Wm1a+Wm1b) ; b_nb = b2@Wn1b ; b_sc = 7*msg_b2@Wn1c
// Step 0 consumes h_0 = x with ORIGINAL weights (pointer ternary).
// Structure (proven 603us): per-GEMM cp.async rings, dual A/B GEMM,
// dual-input node GEMM, xw in smem, 72KB smem, 3 CTAs/SM, ~153 regs.
// ---------------------------------------------------------------------------

#define THREADS 128
#define NG      4
#define MROWS   32
#define BS      2048
#define NSTEPS  8
#define H       128
#define KCH     8                       // k-rows per staged chunk
#define NCHK    (H / KCH)               // 16 chunks per GEMM
#define CHF     (KCH * H)               // 1024 floats = 4KB per chunk

__device__ float g_wsc[H * H];          // msg_w2 @ node_w1[256:384]
__device__ float g_wma[H * H];          // node_w2 @ msg_w1[0:128]
__device__ float g_wmb[H * H];          // node_w2 @ msg_w1[128:256]
__device__ float g_wnb[H * H];          // node_w2 @ node_w1[128:256]
__device__ float g_wpool[H * H];        // node_w2 @ out_w1
__device__ float g_bsc[H];              // 7 * msg_b2 @ node_w1[256:384]
__device__ float g_biass[H];            // msg_b1 + node_b2@(Wm1a + Wm1b)
__device__ float g_bnb[H];              // node_b2 @ node_w1[128:256]
__device__ float g_boh[H];              // 8 * node_b2 @ out_w1 + out_b1

union F2 { float2 f; unsigned long long u; };

__device__ __forceinline__ F2 f2fma(F2 a, F2 b, F2 c) {
    F2 d;
    asm("fma.rn.f32x2 %0, %1, %2, %3;" : "=l"(d.u) : "l"(a.u), "l"(b.u), "l"(c.u));
    return d;
}
__device__ __forceinline__ F2 f2bcast(float x) {
    F2 r; unsigned xi = __float_as_uint(x);
    asm("mov.b64 %0, {%1, %1};" : "=l"(r.u) : "r"(xi));
    return r;
}
__device__ __forceinline__ F2 f2mk(float x, float y) { F2 r; r.f.x = x; r.f.y = y; return r; }

__device__ __forceinline__ void cp_commit() { asm volatile("cp.async.commit_group;" ::: "memory"); }
__device__ __forceinline__ void cp_wait1()  { asm volatile("cp.async.wait_group 1;"  ::: "memory"); }

__device__ __forceinline__ float f4c(const float4& v, int k) {
    return k == 0 ? v.x : k == 1 ? v.y : k == 2 ? v.z : v.w;
}

// ---- prep kernel: composed weights + bias vectors (once per launch) -------
// grid (H, 5): y selects the product, x = output row i, thread = column j.
__global__ void __launch_bounds__(THREADS)
prep_kernel(const float* __restrict__ msg_w1, const float* __restrict__ msg_b1,
            const float* __restrict__ msg_w2, const float* __restrict__ msg_b2,
            const float* __restrict__ node_w1, const float* __restrict__ node_b2,
            const float* __restrict__ node_w2,
            const float* __restrict__ out_w1, const float* __restrict__ out_b1) {
    const int i = blockIdx.x;
    const int j = threadIdx.x;
    const int which = blockIdx.y;
    const float* L; const float* R; float* O;
    if (which == 0)      { L = msg_w2;  R = node_w1 + 256 * H; O = g_wsc; }
    else if (which == 1) { L = node_w2; R = msg_w1;            O = g_wma; }
    else if (which == 2) { L = node_w2; R = msg_w1 + 128 * H;  O = g_wmb; }
    else if (which == 3) { L = node_w2; R = node_w1 + 128 * H; O = g_wnb; }
    else                 { L = node_w2; R = out_w1;            O = g_wpool; }
    float s = 0.f;
    for (int m = 0; m < H; ++m) s += L[i * H + m] * R[m * H + j];
    O[i * H + j] = s;
    if (i == 0) {
        if (which == 0) {
            float b = 0.f;
            for (int m = 0; m < H; ++m) b += msg_b2[m] * (node_w1 + 256 * H)[m * H + j];
            g_bsc[j] = 7.f * b;
        } else if (which == 1) {
            float b = 0.f;
            for (int m = 0; m < H; ++m)
                b += node_b2[m] * (msg_w1[m * H + j] + (msg_w1 + 128 * H)[m * H + j]);
            g_biass[j] = msg_b1[j] + b;
        } else if (which == 3) {
            float b = 0.f;
            for (int m = 0; m < H; ++m) b += node_b2[m] * (node_w1 + 128 * H)[m * H + j];
            g_bnb[j] = b;
        } else if (which == 4) {
            float b = 0.f;
            for (int m = 0; m < H; ++m) b += node_b2[m] * out_w1[m * H + j];
            g_boh[j] = 8.f * b + out_b1[j];
        }
    }
}

// Stage one 8x128 chunk (4KB): 256 float4, 2 per thread, coalesced.
__device__ __forceinline__ void stage_chunk(float* ws, const float* __restrict__ W,
                                            int chunk, int t) {
    const float4* src = reinterpret_cast<const float4*>(W + chunk * CHF) + t;
    unsigned dst = (unsigned)__cvta_generic_to_shared(ws) + t * 16;
#pragma unroll
    for (int i = 0; i < 2; ++i) {
        asm volatile("cp.async.cg.shared.global [%0], [%1], 16;"
                     :: "r"(dst + i * 2048), "l"(src + i * 128) : "memory");
    }
}

__device__ __forceinline__ void chunk_fma(const float* __restrict__ in,
                                          const float* __restrict__ wb,
                                          F2 (&acc)[8][2], int r0, int c0, int kb) {
#pragma unroll
    for (int kk = 0; kk < KCH; kk += 4) {
        float4 a[8];
#pragma unroll
        for (int r = 0; r < 8; ++r)
            a[r] = *reinterpret_cast<const float4*>(in + (r0 + r) * H + kb + kk);
#pragma unroll
        for (int k = 0; k < 4; ++k) {
            float4 wv = *reinterpret_cast<const float4*>(wb + (kk + k) * H + c0);
            F2 w0 = f2mk(wv.x, wv.y), w1 = f2mk(wv.z, wv.w);
#pragma unroll
            for (int r = 0; r < 8; ++r) {
                F2 b = f2bcast(f4c(a[r], k));
                acc[r][0] = f2fma(b, w0, acc[r][0]);
                acc[r][1] = f2fma(b, w1, acc[r][1]);
            }
        }
    }
}

__device__ __forceinline__ int ring_next2(int cur) { return cur + 2 >= 3 ? cur - 1 : cur + 2; }
__device__ __forceinline__ int ring_adv(int cur)   { return cur == 2 ? 0 : cur + 1; }

// acc += in(own rows) @ W, W streamed via 3-buffer cp.async ring (depth 2).
__device__ __forceinline__ void gemm_run(const float* __restrict__ in,
                                         const float* __restrict__ W,
                                         F2 (&acc)[8][2], int r0, int c0, int t,
                                         float* ws) {
    __syncthreads();
    stage_chunk(ws, W, 0, t);            cp_commit();
    stage_chunk(ws + CHF, W, 1, t);      cp_commit();
    int cur = 0;
    for (int ch = 0; ch < NCHK; ++ch) {
        cp_wait1();
        __syncthreads();
        if (ch + 2 < NCHK) stage_chunk(ws + ring_next2(cur) * CHF, W, ch + 2, t);
        cp_commit();
        chunk_fma(in, ws + cur * CHF, acc, r0, c0, ch * KCH);
        cur = ring_adv(cur);
    }
}

// Dual-WEIGHT GEMM sharing activation loads: accA += in@Wa ; accB += in@Wb.
__device__ __forceinline__ void gemm_dual(const float* __restrict__ in,
                                          const float* __restrict__ Wa,
                                          const float* __restrict__ Wb,
                                          F2 (&accA)[8][2], F2 (&accB)[8][2],
                                          int r0, int c0, int t,
                                          float* wsA, float* wsB) {
    __syncthreads();
    stage_chunk(wsA, Wa, 0, t); stage_chunk(wsB, Wb, 0, t); cp_commit();
    stage_chunk(wsA + CHF, Wa, 1, t); stage_chunk(wsB + CHF, Wb, 1, t); cp_commit();
    int cur = 0;
    for (int ch = 0; ch < NCHK; ++ch) {
        cp_wait1();
        __syncthreads();
        if (ch + 2 < NCHK) {
            stage_chunk(wsA + ring_next2(cur) * CHF, Wa, ch + 2, t);
            stage_chunk(wsB + ring_next2(cur) * CHF, Wb, ch + 2, t);
        }
        cp_commit();
        const float* wa = wsA + cur * CHF;
        const float* wbp = wsB + cur * CHF;
        const int kb = ch * KCH;
#pragma unroll
        for (int kk = 0; kk < KCH; kk += 4) {
            float4 a[8];
#pragma unroll
            for (int r = 0; r < 8; ++r)
                a[r] = *reinterpret_cast<const float4*>(in + (r0 + r) * H + kb + kk);
#pragma unroll
            for (int k = 0; k < 4; ++k) {
                float4 wva = *reinterpret_cast<const float4*>(wa + (kk + k) * H + c0);
                float4 wvb = *reinterpret_cast<const float4*>(wbp + (kk + k) * H + c0);
                F2 wa0 = f2mk(wva.x, wva.y), wa1 = f2mk(wva.z, wva.w);
                F2 wb0 = f2mk(wvb.x, wvb.y), wb1 = f2mk(wvb.z, wvb.w);
#pragma unroll
                for (int r = 0; r < 8; ++r) {
                    F2 b = f2bcast(f4c(a[r], k));
                    accA[r][0] = f2fma(b, wa0, accA[r][0]);
                    accA[r][1] = f2fma(b, wa1, accA[r][1]);
                    accB[r][0] = f2fma(b, wb0, accB[r][0]);
                    accB[r][1] = f2fma(b, wb1, accB[r][1]);
                }
            }
        }
        cur = ring_adv(cur);
    }
}

// Dual-INPUT fused GEMM, single accumulator: acc += inA@Wa + inB@Wb.
__device__ __forceinline__ void gemm_dual_in(const float* __restrict__ inA,
                                             const float* __restrict__ Wa,
                                             const float* __restrict__ inB,
                                             const float* __restrict__ Wb,
                                             F2 (&acc)[8][2],
                                             int r0, int c0, int t,
                                             float* wsA, float* wsB) {
    __syncthreads();
    stage_chunk(wsA, Wa, 0, t); stage_chunk(wsB, Wb, 0, t); cp_commit();
    stage_chunk(wsA + CHF, Wa, 1, t); stage_chunk(wsB + CHF, Wb, 1, t); cp_commit();
    int cur = 0;
    for (int ch = 0; ch < NCHK; ++ch) {
        cp_wait1();
        __syncthreads();
        if (ch + 2 < NCHK) {
            stage_chunk(wsA + ring_next2(cur) * CHF, Wa, ch + 2, t);
            stage_chunk(wsB + ring_next2(cur) * CHF, Wb, ch + 2, t);
        }
        cp_commit();
        chunk_fma(inA, wsA + cur * CHF, acc, r0, c0, ch * KCH);
        chunk_fma(inB, wsB + cur * CHF, acc, r0, c0, ch * KCH);
        cur = ring_adv(cur);
    }
}

__device__ __forceinline__ void acc_zero(F2 (&acc)[8][2]) {
#pragma unroll
    for (int r = 0; r < 8; ++r) { acc[r][0] = f2mk(0.f, 0.f); acc[r][1] = f2mk(0.f, 0.f); }
}
__device__ __forceinline__ void acc_bias(F2 (&acc)[8][2], const float* __restrict__ bias,
                                         int c0, float s) {
    float4 b = *reinterpret_cast<const float4*>(bias + c0);
#pragma unroll
    for (int r = 0; r < 8; ++r) {
        acc[r][0] = f2mk(b.x * s, b.y * s);
        acc[r][1] = f2mk(b.z * s, b.w * s);
    }
}
__device__ __forceinline__ void acc_from_smem(F2 (&acc)[8][2], const float* __restrict__ src,
                                              int r0, int c0) {
#pragma unroll
    for (int r = 0; r < 8; ++r) {
        float4 v = *reinterpret_cast<const float4*>(src + (r0 + r) * H + c0);
        acc[r][0] = f2mk(v.x, v.y);
        acc[r][1] = f2mk(v.z, v.w);
    }
}
__device__ __forceinline__ void acc_store(float* __restrict__ out, F2 (&acc)[8][2],
                                          int r0, int c0, bool relu) {
#pragma unroll
    for (int r = 0; r < 8; ++r) {
        float4 v = make_float4(acc[r][0].f.x, acc[r][0].f.y, acc[r][1].f.x, acc[r][1].f.y);
        if (relu) {
            v.x = fmaxf(v.x, 0.f); v.y = fmaxf(v.y, 0.f);
            v.z = fmaxf(v.z, 0.f); v.w = fmaxf(v.w, 0.f);
        }
        *reinterpret_cast<float4*>(out + (r0 + r) * H + c0) = v;
    }
}

__global__ void __launch_bounds__(THREADS)
rrn_kernel(const int* __restrict__ sources, const int* __restrict__ targets,
           const int* __restrict__ types, const int* __restrict__ diffs,
           const int* __restrict__ question,
           const float* __restrict__ pre_w1, const float* __restrict__ pre_b1,
           const float* __restrict__ pre_w2, const float* __restrict__ pre_b2,
           const float* __restrict__ msg_w1, const float* __restrict__ msg_b1,
           const float* __restrict__ node_w1, const float* __restrict__ node_b1,
           const float* __restrict__ out_w2, const float* __restrict__ out_b2,
           float* __restrict__ out)
{
    extern __shared__ float sm[];
    float* sh_h  = sm;                    // carried state: x (step0) then hidden_t
    float* sh_xw = sm + 4096;             // x@Wn1a + node_b1 + b_sc (step-invariant)
    float* sh_S  = sm + 8192;             // scratch: feats / S / poolh / oh
    float* wsA   = sm + 12288;            // cp.async W ring: 2 streams x 3 bufs x 4KB
    float* wsB   = wsA + 3 * CHF;

    const int t    = threadIdx.x;
    const int cta  = blockIdx.x;
    const int warp = t >> 5;              // == graph within CTA
    const int r0   = warp * 8;
    const int c0   = (t & 31) * 4;

    // ---- pre-MLP hidden = relu(one-hot gather of pre_w1 rows + b1) -> sh_S
    {
        const float b1 = pre_b1[t];
        for (int m = 0; m < MROWS; ++m) {
            const int node = cta * MROWS + m;
            const int b  = node >> 3;
            const int s  = sources[node];
            const int tg = targets[node];
            const int ty = types[node];
            const int d  = diffs[node];
            const int q  = question[b];
            float v = pre_w1[s * H + t] + pre_w1[(8 + tg) * H + t]
                    + pre_w1[(16 + ty) * H + t] + pre_w1[(19 + d) * H + t]
                    + pre_w1[(119 + q) * H + t] + b1;
            sh_S[m * H + t] = fmaxf(v, 0.f);
        }
    }
    __syncthreads();

    // ---- x = hidden @ pre_w2 + pre_b2 -> sh_h  (h0 = x)
    {
        F2 acc[8][2];
        acc_bias(acc, pre_b2, c0, 1.0f);
        gemm_run(sh_S, pre_w2, acc, r0, c0, t, wsA);
        acc_store(sh_h, acc, r0, c0, false);
        __syncwarp();
    }

    // ---- xw = x @ node_w1[0:128] + node_b1 + b_sc -> sh_xw  (step-invariant)
    {
        F2 acc[8][2];
        float4 nb = *reinterpret_cast<const float4*>(node_b1 + c0);
        float4 bs = *reinterpret_cast<const float4*>(g_bsc + c0);
#pragma unroll
        for (int r = 0; r < 8; ++r) {
            acc[r][0] = f2mk(nb.x + bs.x, nb.y + bs.y);
            acc[r][1] = f2mk(nb.z + bs.z, nb.w + bs.w);
        }
        gemm_run(sh_h, node_w1, acc, r0, c0, t, wsA);
        acc_store(sh_xw, acc, r0, c0, false);
        __syncwarp();
    }

    // S-phase biases: step0 uses msg_b1; steps>=1 use composed g_biass.
    const float4 b0v = *reinterpret_cast<const float4*>(msg_b1 + c0);
    const float4 bcv = *reinterpret_cast<const float4*>(g_biass + c0);
    const float bias0[4] = {b0v.x, b0v.y, b0v.z, b0v.w};
    const float biasc[4] = {bcv.x, bcv.y, bcv.z, bcv.w};

    for (int step = 0; step < NSTEPS; ++step) {
        const float* Wa = step ? g_wma : msg_w1;
        const float* Wb = step ? g_wmb : msg_w1 + 128 * H;
        const float* Wn = step ? g_wnb : node_w1 + 128 * H;

        // A/B parts (reg-resident); input sh_h = x or hidden_{t-1}
        F2 accA[8][2], accB[8][2];
        acc_zero(accA); acc_zero(accB);
        gemm_dual(sh_h, Wa, Wb, accA, accB, r0, c0, t, wsA, wsB);

        // S_i = sum_{j != i} relu(A_i + B_j + bias)  (into accA)
        {
#pragma unroll
            for (int cc = 0; cc < 4; ++cc) {
                const int p = cc >> 1, hl = cc & 1;
                float A[8], Bv[8];
#pragma unroll
                for (int r = 0; r < 8; ++r) {
                    A[r]  = hl ? accA[r][p].f.y : accA[r][p].f.x;
                    Bv[r] = hl ? accB[r][p].f.y : accB[r][p].f.x;
                }
                const float bc = step ? biasc[cc] : bias0[cc];
#pragma unroll
                for (int i = 0; i < 8; ++i) {
                    float s = 0.f;
#pragma unroll
                    for (int j = 0; j < 8; ++j) s += fmaxf(A[i] + Bv[j] + bc, 0.f);
                    s -= fmaxf(A[i] + Bv[i] + bc, 0.f);    // drop self-edge
                    if (hl) accA[i][p].f.y = s; else accA[i][p].f.x = s;
                }
            }
            acc_store(sh_S, accA, r0, c0, false);          // S -> own slots
            __syncwarp();
        }

        // hidden = relu(xw [+b_nb] + sh_h@Wn + S@W_sc) -> sh_h (in place: own rows)
        {
            F2 acc[8][2];
            acc_from_smem(acc, sh_xw, r0, c0);
            if (step) {
                float4 bn = *reinterpret_cast<const float4*>(g_bnb + c0);
#pragma unroll
                for (int r = 0; r < 8; ++r) {
                    acc[r][0].f.x += bn.x; acc[r][0].f.y += bn.y;
                    acc[r][1].f.x += bn.z; acc[r][1].f.y += bn.w;
                }
            }
            gemm_dual_in(sh_h, Wn, sh_S, g_wsc, acc, r0, c0, t, wsA, wsB);
            acc_store(sh_h, acc, r0, c0, true);
            // poolh = sum over own graph's 8 rows of hidden (post-relu)
            float4 pool = make_float4(0.f, 0.f, 0.f, 0.f);
#pragma unroll
            for (int r = 0; r < 8; ++r) {
                pool.x += fmaxf(acc[r][0].f.x, 0.f); pool.y += fmaxf(acc[r][0].f.y, 0.f);
                pool.z += fmaxf(acc[r][1].f.x, 0.f); pool.w += fmaxf(acc[r][1].f.y, 0.f);
            }
            __syncthreads();               // all warps done reading sh_S (S matrix)
            *reinterpret_cast<float4*>(sh_S + warp * H + c0) = pool;  // row g = graph g
        }
        __syncthreads();

        // oh = relu(poolh @ W_pool + b_oh) -> sh_S rows 4..7  (pooled phase folded)
        {
            float acc[NG];
            const float ob = g_boh[t];
#pragma unroll
            for (int g = 0; g < NG; ++g) acc[g] = ob;
#pragma unroll 8
            for (int k = 0; k < H; ++k) {
                const float w = g_wpool[k * H + t];
#pragma unroll
                for (int g = 0; g < NG; ++g) acc[g] += sh_S[g * H + k] * w;
            }
#pragma unroll
            for (int g = 0; g < NG; ++g) sh_S[(4 + g) * H + t] = fmaxf(acc[g], 0.f);
        }
        __syncthreads();

        // logits = oh @ out_w2 + out_b2 -> gmem [step][bs][100]
        if (t < 100) {
            float acc[NG];
            const float ob = out_b2[t];
#pragma unroll
            for (int g = 0; g < NG; ++g) acc[g] = ob;
#pragma unroll 8
            for (int k = 0; k < H; ++k) {
                const float w = out_w2[k * 100 + t];
#pragma unroll
                for (int g = 0; g < NG; ++g) acc[g] += sh_S[(4 + g) * H + k] * w;
            }
#pragma unroll
            for (int g = 0; g < NG; ++g)
                out[(step * BS + cta * NG + g) * 100 + t] = acc[g];
        }
        // next iteration's gemm_dual begins with its entry __syncthreads
    }
}

extern "C" void kernel_launch(void* const* d_in, const int* in_sizes, int n_in,
                              void* d_out, int out_size) {
    (void)in_sizes; (void)n_in; (void)out_size;
    const int*   sources  = (const int*)  d_in[0];
    const int*   targets  = (const int*)  d_in[1];
    const int*   types    = (const int*)  d_in[2];
    const int*   diffs    = (const int*)  d_in[3];
    const int*   question = (const int*)  d_in[4];
    const float* pre_w1   = (const float*)d_in[5];
    const float* pre_b1   = (const float*)d_in[6];
    const float* pre_w2   = (const float*)d_in[7];
    const float* pre_b2   = (const float*)d_in[8];
    const float* msg_w1   = (const float*)d_in[9];
    const float* msg_b1   = (const float*)d_in[10];
    const float* msg_w2   = (const float*)d_in[11];
    const float* msg_b2   = (const float*)d_in[12];
    const float* node_w1  = (const float*)d_in[13];
    const float* node_b1  = (const float*)d_in[14];
    const float* node_w2  = (const float*)d_in[15];
    const float* node_b2  = (const float*)d_in[16];
    const float* out_w1   = (const float*)d_in[17];
    const float* out_b1   = (const float*)d_in[18];
    const float* out_w2   = (const float*)d_in[19];
    const float* out_b2   = (const float*)d_in[20];

    // prep: composed weights W_sc/W_ma/W_mb/W_nb/W_pool + bias vectors
    prep_kernel<<<dim3(H, 5), THREADS>>>(msg_w1, msg_b1, msg_w2, msg_b2,
                                         node_w1, node_b2, node_w2,
                                         out_w1, out_b1);

    const size_t smem = (3 * 4096 + 6 * CHF) * sizeof(float);  // 48KB + 24KB = 72KB
    cudaFuncSetAttribute(rrn_kernel, cudaFuncAttributeMaxDynamicSharedMemorySize,
                         (int)smem);

    rrn_kernel<<<BS / NG, THREADS, smem>>>(
        sources, targets, types, diffs, question,
        pre_w1, pre_b1, pre_w2, pre_b2,
        msg_w1, msg_b1,
        node_w1, node_b1,
        out_w2, out_b2,
        (float*)d_out);
}